// round 1
// baseline (speedup 1.0000x reference)
#include <cuda_runtime.h>
#include <cuda_bf16.h>

// Problem dims (fixed for this problem instance)
#define ND   2048
#define NM   512
#define IN_  256
#define OC   128
#define NTOT (ND + NM)      // 2560
#define NEDG (NM + 1)       // 513

// ---------------- device scratch (no allocations allowed) ----------------
__device__ float g_xlin[NTOT * OC];     // comb @ W_gat^T
__device__ float g_anode[NTOT];
__device__ float g_ahe[ND];
__device__ float g_E[ND * NM];          // softmax weights for medicine edges
__device__ float g_alpha0[ND];          // softmax weight for the disease edge
__device__ float g_e[ND * OC];          // hyperedge features
__device__ float g_eacc[ND * OC];       // split-K accumulator for gemm2
__device__ float g_macc[NM * OC];       // split-K accumulator for gemm3
__device__ float g_meanc[IN_];          // column-sum of c_embeddings
__device__ float g_meanm[IN_];          // column-sum of m_embeddings
__device__ float g_vb[IN_];             // W_gat^T @ att[OC:]
__device__ float g_convc[OC];
__device__ float g_convm[OC];

__device__ __forceinline__ float lrelu(float x) { return x > 0.f ? x : 0.2f * x; }

// ---------------- zero the accumulators ----------------
__global__ void k_zero() {
    int idx = blockIdx.x * blockDim.x + threadIdx.x;
    int stride = gridDim.x * blockDim.x;
    for (int i = idx; i < ND * OC; i += stride) g_eacc[i] = 0.f;
    for (int i = idx; i < NM * OC; i += stride) g_macc[i] = 0.f;
    if (idx < IN_) { g_meanc[idx] = 0.f; g_meanm[idx] = 0.f; }
}

// ---------------- column sums + vb ----------------
// blocks 0..15: c_embeddings row-chunks of 128; 16..19: m_embeddings; 20: vb
__global__ void k_prep(const float* __restrict__ cemb, const float* __restrict__ memb,
                       const float* __restrict__ Wg,   const float* __restrict__ att) {
    int b = blockIdx.x;
    int t = threadIdx.x;           // 256 threads = one per column
    if (b < 16) {
        const float* base = cemb + (size_t)b * 128 * IN_;
        float s = 0.f;
        for (int r = 0; r < 128; r++) s += base[r * IN_ + t];
        atomicAdd(&g_meanc[t], s);
    } else if (b < 20) {
        const float* base = memb + (size_t)(b - 16) * 128 * IN_;
        float s = 0.f;
        for (int r = 0; r < 128; r++) s += base[r * IN_ + t];
        atomicAdd(&g_meanm[t], s);
    } else {
        // vb[i] = sum_o Wg[o*IN_+i] * att[OC+o]
        float s = 0.f;
        for (int o = 0; o < OC; o++) s += Wg[o * IN_ + t] * att[OC + o];
        g_vb[t] = s;
    }
}

// ---------------- conv broadcast vectors ----------------
__global__ void k_conv(const float* __restrict__ Wc, const float* __restrict__ bc) {
    __shared__ float smc[IN_], smm[IN_];
    int t = threadIdx.x;
    smc[t] = g_meanc[t];
    smm[t] = g_meanm[t];
    __syncthreads();
    if (t < OC) {
        float s = 0.f;
        for (int i = 0; i < IN_; i++) s += Wc[t * IN_ + i] * smc[i];
        g_convc[t] = s * (1.f / ND) + bc[t];
    } else {
        int n = t - OC;
        float s = 0.f;
        for (int i = 0; i < IN_; i++) s += Wc[n * IN_ + i] * smm[i];
        g_convm[n] = s * (1.f / NM) + bc[n];
    }
}

// ---------------- GEMM1: x_lin = comb @ W_gat^T, fused a_node ----------------
// BM=32, BN=128, BK=16, 256 threads, 4x4 per thread. grid = 2560/32 = 80.
__global__ void k_gemm1(const float* __restrict__ cemb, const float* __restrict__ memb,
                        const float* __restrict__ Wg,   const float* __restrict__ att) {
    __shared__ __align__(16) float As[16][32];
    __shared__ __align__(16) float Bs[16][128];
    __shared__ float satt[OC];
    int t = threadIdx.x;
    int m0 = blockIdx.x * 32;
    const float* A = (m0 < ND) ? (cemb + (size_t)m0 * IN_) : (memb + (size_t)(m0 - ND) * IN_);
    if (t < OC) satt[t] = att[t];
    int ty = t >> 5, tx = t & 31;
    float acc[4][4] = {};
    for (int k0 = 0; k0 < IN_; k0 += 16) {
        if (t < 128) {
            int r = t >> 2, kq = (t & 3) * 4;
            float4 v = *(const float4*)(A + r * IN_ + k0 + kq);
            As[kq + 0][r] = v.x; As[kq + 1][r] = v.y; As[kq + 2][r] = v.z; As[kq + 3][r] = v.w;
        }
        {
            int n = t >> 1, kh = (t & 1) * 8;
            float4 v0 = *(const float4*)(Wg + n * IN_ + k0 + kh);
            float4 v1 = *(const float4*)(Wg + n * IN_ + k0 + kh + 4);
            Bs[kh + 0][n] = v0.x; Bs[kh + 1][n] = v0.y; Bs[kh + 2][n] = v0.z; Bs[kh + 3][n] = v0.w;
            Bs[kh + 4][n] = v1.x; Bs[kh + 5][n] = v1.y; Bs[kh + 6][n] = v1.z; Bs[kh + 7][n] = v1.w;
        }
        __syncthreads();
#pragma unroll
        for (int kk = 0; kk < 16; kk++) {
            float a0 = As[kk][ty * 4 + 0], a1 = As[kk][ty * 4 + 1];
            float a2 = As[kk][ty * 4 + 2], a3 = As[kk][ty * 4 + 3];
            float4 b = *(const float4*)&Bs[kk][tx * 4];
            acc[0][0] += a0 * b.x; acc[0][1] += a0 * b.y; acc[0][2] += a0 * b.z; acc[0][3] += a0 * b.w;
            acc[1][0] += a1 * b.x; acc[1][1] += a1 * b.y; acc[1][2] += a1 * b.z; acc[1][3] += a1 * b.w;
            acc[2][0] += a2 * b.x; acc[2][1] += a2 * b.y; acc[2][2] += a2 * b.z; acc[2][3] += a2 * b.w;
            acc[3][0] += a3 * b.x; acc[3][1] += a3 * b.y; acc[3][2] += a3 * b.z; acc[3][3] += a3 * b.w;
        }
        __syncthreads();
    }
    float4 av = *(const float4*)&satt[tx * 4];
#pragma unroll
    for (int i = 0; i < 4; i++) {
        int r = m0 + ty * 4 + i;
        float4 o = make_float4(acc[i][0], acc[i][1], acc[i][2], acc[i][3]);
        *(float4*)&g_xlin[(size_t)r * OC + tx * 4] = o;
        float p = o.x * av.x + o.y * av.y + o.z * av.z + o.w * av.w;
#pragma unroll
        for (int s = 16; s > 0; s >>= 1) p += __shfl_xor_sync(0xffffffffu, p, s);
        if (tx == 0) g_anode[r] = p;
    }
}

// ---------------- a_he = he_attr @ vb ----------------
__global__ void k_ahe(const float* __restrict__ he) {
    __shared__ float svb[IN_];
    int t = threadIdx.x;
    svb[t] = g_vb[t];
    __syncthreads();
    int warp = t >> 5, lane = t & 31;
    int row = blockIdx.x * 8 + warp;
    const float* base = he + (size_t)row * IN_;
    float s = 0.f;
#pragma unroll
    for (int j = 0; j < 8; j++) {
        int i = lane + j * 32;
        s += base[i] * svb[i];
    }
#pragma unroll
    for (int sh = 16; sh > 0; sh >>= 1) s += __shfl_xor_sync(0xffffffffu, s, sh);
    if (lane == 0) g_ahe[row] = s;
}

// ---------------- per-hyperedge softmax (rows of 513) ----------------
// grid 256 blocks x 8 rows, 256 threads.
__global__ void k_softmax() {
    __shared__ float sanm[NM];
    __shared__ float red[256];
    int t = threadIdx.x;
    sanm[t]       = g_anode[ND + t];
    sanm[t + 256] = g_anode[ND + t + 256];
    __syncthreads();
    for (int rr = 0; rr < 8; rr++) {
        int d = blockIdx.x * 8 + rr;
        float ah  = g_ahe[d];
        float l0  = lrelu(g_anode[d] + ah);
        float l1  = lrelu(sanm[t] + ah);
        float l2  = lrelu(sanm[t + 256] + ah);
        float mx = fmaxf(l1, l2);
        red[t] = mx; __syncthreads();
        for (int s = 128; s > 0; s >>= 1) { if (t < s) red[t] = fmaxf(red[t], red[t + s]); __syncthreads(); }
        float M = fmaxf(red[0], l0);
        __syncthreads();
        float e1 = __expf(l1 - M), e2 = __expf(l2 - M);
        red[t] = e1 + e2; __syncthreads();
        for (int s = 128; s > 0; s >>= 1) { if (t < s) red[t] += red[t + s]; __syncthreads(); }
        float e0 = __expf(l0 - M);
        float inv = 1.f / (red[0] + e0);
        g_E[(size_t)d * NM + t]       = e1 * inv;
        g_E[(size_t)d * NM + 256 + t] = e2 * inv;
        if (t == 0) g_alpha0[d] = e0 * inv;
        __syncthreads();
    }
}

// ---------------- GEMM2: eacc = E @ x_lin_med  (M=2048, N=128, K=512) ----------------
// grid (64, 2) split-K; atomicAdd into g_eacc
__global__ void k_gemm2() {
    __shared__ __align__(16) float As[16][32];
    __shared__ __align__(16) float Bs[16][128];
    int t = threadIdx.x;
    int m0 = blockIdx.x * 32;
    int kbase = blockIdx.y * 256;
    int ty = t >> 5, tx = t & 31;
    float acc[4][4] = {};
    for (int kt = 0; kt < 16; kt++) {
        int k0 = kbase + kt * 16;
        if (t < 128) {
            int r = t >> 2, kq = (t & 3) * 4;
            float4 v = *(const float4*)(&g_E[(size_t)(m0 + r) * NM + k0 + kq]);
            As[kq + 0][r] = v.x; As[kq + 1][r] = v.y; As[kq + 2][r] = v.z; As[kq + 3][r] = v.w;
        }
#pragma unroll
        for (int it = 0; it < 2; it++) {
            int k = (t >> 5) + it * 8;
            int n4 = (t & 31) * 4;
            float4 v = *(const float4*)(&g_xlin[(size_t)(ND + k0 + k) * OC + n4]);
            *(float4*)&Bs[k][n4] = v;
        }
        __syncthreads();
#pragma unroll
        for (int kk = 0; kk < 16; kk++) {
            float a0 = As[kk][ty * 4 + 0], a1 = As[kk][ty * 4 + 1];
            float a2 = As[kk][ty * 4 + 2], a3 = As[kk][ty * 4 + 3];
            float4 b = *(const float4*)&Bs[kk][tx * 4];
            acc[0][0] += a0 * b.x; acc[0][1] += a0 * b.y; acc[0][2] += a0 * b.z; acc[0][3] += a0 * b.w;
            acc[1][0] += a1 * b.x; acc[1][1] += a1 * b.y; acc[1][2] += a1 * b.z; acc[1][3] += a1 * b.w;
            acc[2][0] += a2 * b.x; acc[2][1] += a2 * b.y; acc[2][2] += a2 * b.z; acc[2][3] += a2 * b.w;
            acc[3][0] += a3 * b.x; acc[3][1] += a3 * b.y; acc[3][2] += a3 * b.z; acc[3][3] += a3 * b.w;
        }
        __syncthreads();
    }
#pragma unroll
    for (int i = 0; i < 4; i++) {
        int r = m0 + ty * 4 + i;
#pragma unroll
        for (int j = 0; j < 4; j++)
            atomicAdd(&g_eacc[(size_t)r * OC + tx * 4 + j], acc[i][j]);
    }
}

// ---------------- epilogue 1: e, disease output rows ----------------
__global__ void k_epi1(const float* __restrict__ bg, float* __restrict__ out) {
    int idx = blockIdx.x * blockDim.x + threadIdx.x;   // ND*OC threads
    int d = idx >> 7, n = idx & 127;
    float a0 = g_alpha0[d];
    float e  = (a0 * g_xlin[(size_t)d * OC + n] + g_eacc[idx]) * (1.f / NEDG);
    g_e[idx] = e;
    out[(size_t)d * (2 * OC) + n]      = a0 * e + bg[n];
    out[(size_t)d * (2 * OC) + OC + n] = g_convc[n];
}

// ---------------- GEMM3: macc = E^T @ e  (M=512, N=128, K=2048) ----------------
// grid (16, 8) split-K; atomicAdd into g_macc
__global__ void k_gemm3() {
    __shared__ __align__(16) float As[16][32];
    __shared__ __align__(16) float Bs[16][128];
    int t = threadIdx.x;
    int m0 = blockIdx.x * 32;
    int kbase = blockIdx.y * 256;
    int ty = t >> 5, tx = t & 31;
    float acc[4][4] = {};
    for (int kt = 0; kt < 16; kt++) {
        int k0 = kbase + kt * 16;
        if (t < 128) {
            int k = t >> 3, mq = (t & 7) * 4;
            float4 v = *(const float4*)(&g_E[(size_t)(k0 + k) * NM + m0 + mq]);
            *(float4*)&As[k][mq] = v;
        }
#pragma unroll
        for (int it = 0; it < 2; it++) {
            int k = (t >> 5) + it * 8;
            int n4 = (t & 31) * 4;
            float4 v = *(const float4*)(&g_e[(size_t)(k0 + k) * OC + n4]);
            *(float4*)&Bs[k][n4] = v;
        }
        __syncthreads();
#pragma unroll
        for (int kk = 0; kk < 16; kk++) {
            float a0 = As[kk][ty * 4 + 0], a1 = As[kk][ty * 4 + 1];
            float a2 = As[kk][ty * 4 + 2], a3 = As[kk][ty * 4 + 3];
            float4 b = *(const float4*)&Bs[kk][tx * 4];
            acc[0][0] += a0 * b.x; acc[0][1] += a0 * b.y; acc[0][2] += a0 * b.z; acc[0][3] += a0 * b.w;
            acc[1][0] += a1 * b.x; acc[1][1] += a1 * b.y; acc[1][2] += a1 * b.z; acc[1][3] += a1 * b.w;
            acc[2][0] += a2 * b.x; acc[2][1] += a2 * b.y; acc[2][2] += a2 * b.z; acc[2][3] += a2 * b.w;
            acc[3][0] += a3 * b.x; acc[3][1] += a3 * b.y; acc[3][2] += a3 * b.z; acc[3][3] += a3 * b.w;
        }
        __syncthreads();
    }
#pragma unroll
    for (int i = 0; i < 4; i++) {
        int r = m0 + ty * 4 + i;
#pragma unroll
        for (int j = 0; j < 4; j++)
            atomicAdd(&g_macc[(size_t)r * OC + tx * 4 + j], acc[i][j]);
    }
}

// ---------------- epilogue 2: medicine output rows ----------------
__global__ void k_epi2(const float* __restrict__ bg, float* __restrict__ out) {
    int idx = blockIdx.x * blockDim.x + threadIdx.x;   // NM*OC threads
    int m = idx >> 7, n = idx & 127;
    out[(size_t)(ND + m) * (2 * OC) + n]      = g_macc[idx] * (1.f / ND) + bg[n];
    out[(size_t)(ND + m) * (2 * OC) + OC + n] = g_convm[n];
}

// ---------------- launch ----------------
extern "C" void kernel_launch(void* const* d_in, const int* in_sizes, int n_in,
                              void* d_out, int out_size) {
    const float* cemb = (const float*)d_in[2];
    const float* memb = (const float*)d_in[3];
    const float* Wc   = (const float*)d_in[4];
    const float* bc   = (const float*)d_in[5];
    const float* Wg   = (const float*)d_in[6];
    const float* att  = (const float*)d_in[7];
    const float* bg   = (const float*)d_in[8];
    const float* he   = (const float*)d_in[9];
    float* out = (float*)d_out;

    k_zero<<<256, 256>>>();
    k_prep<<<21, 256>>>(cemb, memb, Wg, att);
    k_conv<<<1, 256>>>(Wc, bc);
    k_gemm1<<<NTOT / 32, 256>>>(cemb, memb, Wg, att);
    k_ahe<<<ND / 8, 256>>>(he);
    k_softmax<<<ND / 8, 256>>>();
    k_gemm2<<<dim3(ND / 32, 2), 256>>>();
    k_epi1<<<ND * OC / 256, 256>>>(bg, out);
    k_gemm3<<<dim3(NM / 32, 8), 256>>>();
    k_epi2<<<NM * OC / 256, 256>>>(bg, out);
}

// round 4
// speedup vs baseline: 1.1045x; 1.1045x over previous
#include <cuda_runtime.h>
#include <cuda_bf16.h>

// Problem dims (fixed for this problem instance)
#define ND   2048
#define NM   512
#define IN_  256
#define OC   128
#define NTOT (ND + NM)      // 2560
#define NEDG (NM + 1)       // 513

// ---------------- device scratch (no allocations allowed) ----------------
__device__ float g_xlin[NTOT * OC];     // comb @ W_gat^T (split-K atomic target)
__device__ float g_anode[NTOT];         // x_lin @ att[:OC] (split-K atomic target)
__device__ float g_ahe[ND];
__device__ float g_E[ND * NM];          // softmax weights for medicine edges
__device__ float g_alpha0[ND];          // softmax weight for the disease edge
__device__ float g_e[ND * OC];          // hyperedge features
__device__ float g_eacc[ND * OC];       // split-K accumulator for gemm2
__device__ float g_macc[NM * OC];       // split-K accumulator for gemm3
__device__ float g_meanc[IN_];          // column-sum of c_embeddings
__device__ float g_meanm[IN_];          // column-sum of m_embeddings
__device__ float g_vb[IN_];             // W_gat^T @ att[OC:]
__device__ float g_convc[OC];
__device__ float g_convm[OC];

__device__ __forceinline__ float lrelu(float x) { return x > 0.f ? x : 0.2f * x; }

// ---------------- zero all atomic accumulators ----------------
__global__ void k_zero() {
    int idx = blockIdx.x * blockDim.x + threadIdx.x;
    int stride = gridDim.x * blockDim.x;
    for (int i = idx; i < NTOT * OC; i += stride) g_xlin[i] = 0.f;
    for (int i = idx; i < ND * OC; i += stride) g_eacc[i] = 0.f;
    for (int i = idx; i < NM * OC; i += stride) g_macc[i] = 0.f;
    if (idx < NTOT) g_anode[idx] = 0.f;
    if (idx < IN_) { g_meanc[idx] = 0.f; g_meanm[idx] = 0.f; }
}

// ---------------- column sums + vb ----------------
__global__ void k_prep(const float* __restrict__ cemb, const float* __restrict__ memb,
                       const float* __restrict__ Wg,   const float* __restrict__ att) {
    int b = blockIdx.x;
    int t = threadIdx.x;           // 256 threads = one per column
    if (b < 16) {
        const float* base = cemb + (size_t)b * 128 * IN_;
        float s = 0.f;
        for (int r = 0; r < 128; r++) s += base[r * IN_ + t];
        atomicAdd(&g_meanc[t], s);
    } else if (b < 20) {
        const float* base = memb + (size_t)(b - 16) * 128 * IN_;
        float s = 0.f;
        for (int r = 0; r < 128; r++) s += base[r * IN_ + t];
        atomicAdd(&g_meanm[t], s);
    } else {
        float s = 0.f;
        for (int o = 0; o < OC; o++) s += Wg[o * IN_ + t] * att[OC + o];
        g_vb[t] = s;
    }
}

// ---------------- conv broadcast vectors ----------------
__global__ void k_conv(const float* __restrict__ Wc, const float* __restrict__ bc) {
    __shared__ float smc[IN_], smm[IN_];
    int t = threadIdx.x;
    smc[t] = g_meanc[t];
    smm[t] = g_meanm[t];
    __syncthreads();
    if (t < OC) {
        float s = 0.f;
        for (int i = 0; i < IN_; i++) s += Wc[t * IN_ + i] * smc[i];
        g_convc[t] = s * (1.f / ND) + bc[t];
    } else {
        int n = t - OC;
        float s = 0.f;
        for (int i = 0; i < IN_; i++) s += Wc[n * IN_ + i] * smm[i];
        g_convm[n] = s * (1.f / NM) + bc[n];
    }
}

// ---------------- GEMM1: x_lin = comb @ W_gat^T, fused partial a_node ----------------
// BM=32, BN=128, split-K x4 (K-chunk 64). grid (80, 4) = 320 CTAs.
__global__ void k_gemm1(const float* __restrict__ cemb, const float* __restrict__ memb,
                        const float* __restrict__ Wg,   const float* __restrict__ att) {
    __shared__ __align__(16) float As[16][32];
    __shared__ __align__(16) float Bs[16][128];
    __shared__ float satt[OC];
    int t = threadIdx.x;
    int m0 = blockIdx.x * 32;
    int kbase = blockIdx.y * 64;
    const float* A = (m0 < ND) ? (cemb + (size_t)m0 * IN_) : (memb + (size_t)(m0 - ND) * IN_);
    if (t < OC) satt[t] = att[t];
    int ty = t >> 5, tx = t & 31;
    float acc[4][4] = {};
#pragma unroll
    for (int kt = 0; kt < 4; kt++) {
        int k0 = kbase + kt * 16;
        if (t < 128) {
            int r = t >> 2, kq = (t & 3) * 4;
            float4 v = *(const float4*)(A + r * IN_ + k0 + kq);
            As[kq + 0][r] = v.x; As[kq + 1][r] = v.y; As[kq + 2][r] = v.z; As[kq + 3][r] = v.w;
        }
        {
            int n = t >> 1, kh = (t & 1) * 8;
            float4 v0 = *(const float4*)(Wg + n * IN_ + k0 + kh);
            float4 v1 = *(const float4*)(Wg + n * IN_ + k0 + kh + 4);
            Bs[kh + 0][n] = v0.x; Bs[kh + 1][n] = v0.y; Bs[kh + 2][n] = v0.z; Bs[kh + 3][n] = v0.w;
            Bs[kh + 4][n] = v1.x; Bs[kh + 5][n] = v1.y; Bs[kh + 6][n] = v1.z; Bs[kh + 7][n] = v1.w;
        }
        __syncthreads();
#pragma unroll
        for (int kk = 0; kk < 16; kk++) {
            float a0 = As[kk][ty * 4 + 0], a1 = As[kk][ty * 4 + 1];
            float a2 = As[kk][ty * 4 + 2], a3 = As[kk][ty * 4 + 3];
            float4 b = *(const float4*)&Bs[kk][tx * 4];
            acc[0][0] += a0 * b.x; acc[0][1] += a0 * b.y; acc[0][2] += a0 * b.z; acc[0][3] += a0 * b.w;
            acc[1][0] += a1 * b.x; acc[1][1] += a1 * b.y; acc[1][2] += a1 * b.z; acc[1][3] += a1 * b.w;
            acc[2][0] += a2 * b.x; acc[2][1] += a2 * b.y; acc[2][2] += a2 * b.z; acc[2][3] += a2 * b.w;
            acc[3][0] += a3 * b.x; acc[3][1] += a3 * b.y; acc[3][2] += a3 * b.z; acc[3][3] += a3 * b.w;
        }
        __syncthreads();
    }
    float4 av = *(const float4*)&satt[tx * 4];
#pragma unroll
    for (int i = 0; i < 4; i++) {
        int r = m0 + ty * 4 + i;
        float* dst = &g_xlin[(size_t)r * OC + tx * 4];
        atomicAdd(dst + 0, acc[i][0]); atomicAdd(dst + 1, acc[i][1]);
        atomicAdd(dst + 2, acc[i][2]); atomicAdd(dst + 3, acc[i][3]);
        // partial a_node for this K-split (linear in x_lin, so split-distributable)
        float p = acc[i][0] * av.x + acc[i][1] * av.y + acc[i][2] * av.z + acc[i][3] * av.w;
#pragma unroll
        for (int s = 16; s > 0; s >>= 1) p += __shfl_xor_sync(0xffffffffu, p, s);
        if (tx == 0) atomicAdd(&g_anode[r], p);
    }
}

// ---------------- a_he = he_attr @ vb ----------------
__global__ void k_ahe(const float* __restrict__ he) {
    __shared__ float svb[IN_];
    int t = threadIdx.x;
    svb[t] = g_vb[t];
    __syncthreads();
    int warp = t >> 5, lane = t & 31;
    int row = blockIdx.x * 8 + warp;
    const float* base = he + (size_t)row * IN_;
    float s = 0.f;
#pragma unroll
    for (int j = 0; j < 8; j++) {
        int i = lane + j * 32;
        s += base[i] * svb[i];
    }
#pragma unroll
    for (int sh = 16; sh > 0; sh >>= 1) s += __shfl_xor_sync(0xffffffffu, s, sh);
    if (lane == 0) g_ahe[row] = s;
}

// ---------------- per-hyperedge softmax: one WARP per row of 513 ----------------
// grid 256 blocks x 8 warps = 2048 rows.
__global__ void k_softmax() {
    __shared__ float sanm[NM];
    int t = threadIdx.x;
    sanm[t]       = g_anode[ND + t];
    sanm[t + 256] = g_anode[ND + t + 256];
    __syncthreads();
    int w = t >> 5, lane = t & 31;
    int d = blockIdx.x * 8 + w;
    float ah = g_ahe[d];
    float l[16];
    float mx = -1e30f;
#pragma unroll
    for (int j = 0; j < 16; j++) {
        l[j] = lrelu(sanm[lane + j * 32] + ah);
        mx = fmaxf(mx, l[j]);
    }
    float l0 = lrelu(g_anode[d] + ah);   // broadcast load, same on all lanes
    mx = fmaxf(mx, l0);
#pragma unroll
    for (int s = 16; s > 0; s >>= 1) mx = fmaxf(mx, __shfl_xor_sync(0xffffffffu, mx, s));
    float psum = 0.f;
#pragma unroll
    for (int j = 0; j < 16; j++) {
        l[j] = __expf(l[j] - mx);
        psum += l[j];
    }
#pragma unroll
    for (int s = 16; s > 0; s >>= 1) psum += __shfl_xor_sync(0xffffffffu, psum, s);
    float e0 = __expf(l0 - mx);          // identical on all lanes
    float inv = 1.f / (psum + e0);
#pragma unroll
    for (int j = 0; j < 16; j++)
        g_E[(size_t)d * NM + lane + j * 32] = l[j] * inv;
    if (lane == 0) g_alpha0[d] = e0 * inv;
}

// ---------------- GEMM2: eacc = E @ x_lin_med  (M=2048, N=128, K=512) ----------------
// split-K x4 (K-chunk 128). grid (64, 4) = 256 CTAs.
__global__ void k_gemm2() {
    __shared__ __align__(16) float As[16][32];
    __shared__ __align__(16) float Bs[16][128];
    int t = threadIdx.x;
    int m0 = blockIdx.x * 32;
    int kbase = blockIdx.y * 128;
    int ty = t >> 5, tx = t & 31;
    float acc[4][4] = {};
#pragma unroll
    for (int kt = 0; kt < 8; kt++) {
        int k0 = kbase + kt * 16;
        if (t < 128) {
            int r = t >> 2, kq = (t & 3) * 4;
            float4 v = *(const float4*)(&g_E[(size_t)(m0 + r) * NM + k0 + kq]);
            As[kq + 0][r] = v.x; As[kq + 1][r] = v.y; As[kq + 2][r] = v.z; As[kq + 3][r] = v.w;
        }
#pragma unroll
        for (int it = 0; it < 2; it++) {
            int k = (t >> 5) + it * 8;
            int n4 = (t & 31) * 4;
            float4 v = *(const float4*)(&g_xlin[(size_t)(ND + k0 + k) * OC + n4]);
            *(float4*)&Bs[k][n4] = v;
        }
        __syncthreads();
#pragma unroll
        for (int kk = 0; kk < 16; kk++) {
            float a0 = As[kk][ty * 4 + 0], a1 = As[kk][ty * 4 + 1];
            float a2 = As[kk][ty * 4 + 2], a3 = As[kk][ty * 4 + 3];
            float4 b = *(const float4*)&Bs[kk][tx * 4];
            acc[0][0] += a0 * b.x; acc[0][1] += a0 * b.y; acc[0][2] += a0 * b.z; acc[0][3] += a0 * b.w;
            acc[1][0] += a1 * b.x; acc[1][1] += a1 * b.y; acc[1][2] += a1 * b.z; acc[1][3] += a1 * b.w;
            acc[2][0] += a2 * b.x; acc[2][1] += a2 * b.y; acc[2][2] += a2 * b.z; acc[2][3] += a2 * b.w;
            acc[3][0] += a3 * b.x; acc[3][1] += a3 * b.y; acc[3][2] += a3 * b.z; acc[3][3] += a3 * b.w;
        }
        __syncthreads();
    }
#pragma unroll
    for (int i = 0; i < 4; i++) {
        int r = m0 + ty * 4 + i;
        float* dst = &g_eacc[(size_t)r * OC + tx * 4];
        atomicAdd(dst + 0, acc[i][0]); atomicAdd(dst + 1, acc[i][1]);
        atomicAdd(dst + 2, acc[i][2]); atomicAdd(dst + 3, acc[i][3]);
    }
}

// ---------------- epilogue 1: e, disease output rows ----------------
__global__ void k_epi1(const float* __restrict__ bg, float* __restrict__ out) {
    int idx = blockIdx.x * blockDim.x + threadIdx.x;   // ND*OC threads
    int d = idx >> 7, n = idx & 127;
    float a0 = g_alpha0[d];
    float e  = (a0 * g_xlin[(size_t)d * OC + n] + g_eacc[idx]) * (1.f / NEDG);
    g_e[idx] = e;
    out[(size_t)d * (2 * OC) + n]      = a0 * e + bg[n];
    out[(size_t)d * (2 * OC) + OC + n] = g_convc[n];
}

// ---------------- GEMM3: macc = E^T @ e  (M=512, N=128, K=2048) ----------------
// split-K x16 (K-chunk 128). grid (16, 16) = 256 CTAs.
__global__ void k_gemm3() {
    __shared__ __align__(16) float As[16][32];
    __shared__ __align__(16) float Bs[16][128];
    int t = threadIdx.x;
    int m0 = blockIdx.x * 32;
    int kbase = blockIdx.y * 128;
    int ty = t >> 5, tx = t & 31;
    float acc[4][4] = {};
#pragma unroll
    for (int kt = 0; kt < 8; kt++) {
        int k0 = kbase + kt * 16;
        if (t < 128) {
            int k = t >> 3, mq = (t & 7) * 4;
            float4 v = *(const float4*)(&g_E[(size_t)(k0 + k) * NM + m0 + mq]);
            *(float4*)&As[k][mq] = v;
        }
#pragma unroll
        for (int it = 0; it < 2; it++) {
            int k = (t >> 5) + it * 8;
            int n4 = (t & 31) * 4;
            float4 v = *(const float4*)(&g_e[(size_t)(k0 + k) * OC + n4]);
            *(float4*)&Bs[k][n4] = v;
        }
        __syncthreads();
#pragma unroll
        for (int kk = 0; kk < 16; kk++) {
            float a0 = As[kk][ty * 4 + 0], a1 = As[kk][ty * 4 + 1];
            float a2 = As[kk][ty * 4 + 2], a3 = As[kk][ty * 4 + 3];
            float4 b = *(const float4*)&Bs[kk][tx * 4];
            acc[0][0] += a0 * b.x; acc[0][1] += a0 * b.y; acc[0][2] += a0 * b.z; acc[0][3] += a0 * b.w;
            acc[1][0] += a1 * b.x; acc[1][1] += a1 * b.y; acc[1][2] += a1 * b.z; acc[1][3] += a1 * b.w;
            acc[2][0] += a2 * b.x; acc[2][1] += a2 * b.y; acc[2][2] += a2 * b.z; acc[2][3] += a2 * b.w;
            acc[3][0] += a3 * b.x; acc[3][1] += a3 * b.y; acc[3][2] += a3 * b.z; acc[3][3] += a3 * b.w;
        }
        __syncthreads();
    }
#pragma unroll
    for (int i = 0; i < 4; i++) {
        int r = m0 + ty * 4 + i;
        float* dst = &g_macc[(size_t)r * OC + tx * 4];
        atomicAdd(dst + 0, acc[i][0]); atomicAdd(dst + 1, acc[i][1]);
        atomicAdd(dst + 2, acc[i][2]); atomicAdd(dst + 3, acc[i][3]);
    }
}

// ---------------- epilogue 2: medicine output rows ----------------
__global__ void k_epi2(const float* __restrict__ bg, float* __restrict__ out) {
    int idx = blockIdx.x * blockDim.x + threadIdx.x;   // NM*OC threads
    int m = idx >> 7, n = idx & 127;
    out[(size_t)(ND + m) * (2 * OC) + n]      = g_macc[idx] * (1.f / ND) + bg[n];
    out[(size_t)(ND + m) * (2 * OC) + OC + n] = g_convm[n];
}

// ---------------- launch ----------------
extern "C" void kernel_launch(void* const* d_in, const int* in_sizes, int n_in,
                              void* d_out, int out_size) {
    const float* cemb = (const float*)d_in[2];
    const float* memb = (const float*)d_in[3];
    const float* Wc   = (const float*)d_in[4];
    const float* bc   = (const float*)d_in[5];
    const float* Wg   = (const float*)d_in[6];
    const float* att  = (const float*)d_in[7];
    const float* bg   = (const float*)d_in[8];
    const float* he   = (const float*)d_in[9];
    float* out = (float*)d_out;

    k_zero<<<512, 256>>>();
    k_prep<<<21, 256>>>(cemb, memb, Wg, att);
    k_conv<<<1, 256>>>(Wc, bc);
    k_gemm1<<<dim3(NTOT / 32, 4), 256>>>(cemb, memb, Wg, att);
    k_ahe<<<ND / 8, 256>>>(he);
    k_softmax<<<ND / 8, 256>>>();
    k_gemm2<<<dim3(ND / 32, 4), 256>>>();
    k_epi1<<<ND * OC / 256, 256>>>(bg, out);
    k_gemm3<<<dim3(NM / 32, 16), 256>>>();
    k_epi2<<<NM * OC / 256, 256>>>(bg, out);
}

// round 7
// speedup vs baseline: 1.1996x; 1.0861x over previous
#include <cuda_runtime.h>
#include <cuda_bf16.h>

// Problem dims (fixed for this problem instance)
#define ND   2048
#define NM   512
#define IN_  256
#define OC   128
#define NTOT (ND + NM)      // 2560
#define NEDG (NM + 1)       // 513

// ---------------- device scratch (no allocations allowed) ----------------
__device__ float g_xlin[NTOT * OC];     // comb @ W_gat^T (split-K atomic target)
__device__ float g_anode[NTOT];         // x_lin @ att[:OC] (split-K atomic target)
__device__ float g_E[ND * NM];          // softmax weights for medicine edges
__device__ float g_alpha0[ND];          // softmax weight for the disease edge
__device__ float g_e[ND * OC];          // hyperedge features
__device__ float g_eacc[ND * OC];       // split-K accumulator for gemm2
__device__ float g_macc[NM * OC];       // split-K accumulator for gemm3
__device__ float g_meanc[IN_];          // column-sum of c_embeddings
__device__ float g_meanm[IN_];          // column-sum of m_embeddings
__device__ float g_vb[IN_];             // W_gat^T @ att[OC:]
__device__ float g_convc[OC];
__device__ float g_convm[OC];

__device__ __forceinline__ float lrelu(float x) { return x > 0.f ? x : 0.2f * x; }

// ---------------- zero all atomic accumulators ----------------
__global__ void k_zero() {
    int idx = blockIdx.x * blockDim.x + threadIdx.x;
    int stride = gridDim.x * blockDim.x;
    for (int i = idx; i < NTOT * OC; i += stride) g_xlin[i] = 0.f;
    for (int i = idx; i < ND * OC; i += stride) g_eacc[i] = 0.f;
    for (int i = idx; i < NM * OC; i += stride) g_macc[i] = 0.f;
    if (idx < NTOT) g_anode[idx] = 0.f;
    if (idx < IN_) { g_meanc[idx] = 0.f; g_meanm[idx] = 0.f; }
}

// ---------------- column sums + vb ----------------
// blocks 0..63: cemb 32-row chunks; 64..79: memb 32-row chunks; 80: vb
__global__ void k_prep(const float* __restrict__ cemb, const float* __restrict__ memb,
                       const float* __restrict__ Wg,   const float* __restrict__ att) {
    int b = blockIdx.x;
    int t = threadIdx.x;           // 256 threads = one per column
    if (b < 64) {
        const float* base = cemb + (size_t)b * 32 * IN_;
        float s = 0.f;
#pragma unroll
        for (int r = 0; r < 32; r++) s += base[r * IN_ + t];
        atomicAdd(&g_meanc[t], s);
    } else if (b < 80) {
        const float* base = memb + (size_t)(b - 64) * 32 * IN_;
        float s = 0.f;
#pragma unroll
        for (int r = 0; r < 32; r++) s += base[r * IN_ + t];
        atomicAdd(&g_meanm[t], s);
    } else {
        float s = 0.f;
        for (int o = 0; o < OC; o++) s += Wg[o * IN_ + t] * att[OC + o];
        g_vb[t] = s;
    }
}

// ---------------- conv broadcast vectors ----------------
__global__ void k_conv(const float* __restrict__ Wc, const float* __restrict__ bc) {
    __shared__ float smc[IN_], smm[IN_];
    int t = threadIdx.x;
    smc[t] = g_meanc[t];
    smm[t] = g_meanm[t];
    __syncthreads();
    if (t < OC) {
        float s = 0.f;
        for (int i = 0; i < IN_; i++) s += Wc[t * IN_ + i] * smc[i];
        g_convc[t] = s * (1.f / ND) + bc[t];
    } else {
        int n = t - OC;
        float s = 0.f;
        for (int i = 0; i < IN_; i++) s += Wc[n * IN_ + i] * smm[i];
        g_convm[n] = s * (1.f / NM) + bc[n];
    }
}

// ======== GEMM inner-product macro: 8x4 per-thread tile ========
#define MMA_STEP(AS, BS)                                                        \
    _Pragma("unroll")                                                           \
    for (int kk = 0; kk < 16; kk++) {                                           \
        float4 a0 = *(const float4*)&AS[kk][ty * 8];                            \
        float4 a1 = *(const float4*)&AS[kk][ty * 8 + 4];                        \
        float4 b  = *(const float4*)&BS[kk][tx * 4];                            \
        acc[0][0] += a0.x * b.x; acc[0][1] += a0.x * b.y; acc[0][2] += a0.x * b.z; acc[0][3] += a0.x * b.w; \
        acc[1][0] += a0.y * b.x; acc[1][1] += a0.y * b.y; acc[1][2] += a0.y * b.z; acc[1][3] += a0.y * b.w; \
        acc[2][0] += a0.z * b.x; acc[2][1] += a0.z * b.y; acc[2][2] += a0.z * b.z; acc[2][3] += a0.z * b.w; \
        acc[3][0] += a0.w * b.x; acc[3][1] += a0.w * b.y; acc[3][2] += a0.w * b.z; acc[3][3] += a0.w * b.w; \
        acc[4][0] += a1.x * b.x; acc[4][1] += a1.x * b.y; acc[4][2] += a1.x * b.z; acc[4][3] += a1.x * b.w; \
        acc[5][0] += a1.y * b.x; acc[5][1] += a1.y * b.y; acc[5][2] += a1.y * b.z; acc[5][3] += a1.y * b.w; \
        acc[6][0] += a1.z * b.x; acc[6][1] += a1.z * b.y; acc[6][2] += a1.z * b.z; acc[6][3] += a1.z * b.w; \
        acc[7][0] += a1.w * b.x; acc[7][1] += a1.w * b.y; acc[7][2] += a1.w * b.z; acc[7][3] += a1.w * b.w; \
    }

// ---------------- GEMM1: x_lin = comb @ W_gat^T, fused partial a_node ----------------
// BM=64, BN=128, BK=16, split-K x4 (chunk 64). grid (40, 4) = 160 CTAs.
__global__ void k_gemm1(const float* __restrict__ cemb, const float* __restrict__ memb,
                        const float* __restrict__ Wg,   const float* __restrict__ att) {
    __shared__ __align__(16) float As[16][68];
    __shared__ __align__(16) float Bs[16][128];
    __shared__ float satt[OC];
    int t = threadIdx.x;
    int m0 = blockIdx.x * 64;
    int kbase = blockIdx.y * 64;
    const float* A = (m0 < ND) ? (cemb + (size_t)m0 * IN_) : (memb + (size_t)(m0 - ND) * IN_);
    if (t < OC) satt[t] = att[t];
    int ty = t >> 5, tx = t & 31;
    float acc[8][4] = {};
#pragma unroll
    for (int kt = 0; kt < 4; kt++) {
        int k0 = kbase + kt * 16;
        {   // A tile: 64 rows x 16 k, transpose into As[k][row]
            int r = t >> 2, kq = (t & 3) * 4;
            float4 v = *(const float4*)(A + (size_t)r * IN_ + k0 + kq);
            As[kq + 0][r] = v.x; As[kq + 1][r] = v.y; As[kq + 2][r] = v.z; As[kq + 3][r] = v.w;
        }
        {   // B tile from Wg (naturally k-contiguous per n)
            int n = t >> 1, kh = (t & 1) * 8;
            float4 v0 = *(const float4*)(Wg + (size_t)n * IN_ + k0 + kh);
            float4 v1 = *(const float4*)(Wg + (size_t)n * IN_ + k0 + kh + 4);
            Bs[kh + 0][n] = v0.x; Bs[kh + 1][n] = v0.y; Bs[kh + 2][n] = v0.z; Bs[kh + 3][n] = v0.w;
            Bs[kh + 4][n] = v1.x; Bs[kh + 5][n] = v1.y; Bs[kh + 6][n] = v1.z; Bs[kh + 7][n] = v1.w;
        }
        __syncthreads();
        MMA_STEP(As, Bs)
        __syncthreads();
    }
    float4 av = *(const float4*)&satt[tx * 4];
#pragma unroll
    for (int i = 0; i < 8; i++) {
        int r = m0 + ty * 8 + i;
        float* dst = &g_xlin[(size_t)r * OC + tx * 4];
        atomicAdd(dst + 0, acc[i][0]); atomicAdd(dst + 1, acc[i][1]);
        atomicAdd(dst + 2, acc[i][2]); atomicAdd(dst + 3, acc[i][3]);
        float p = acc[i][0] * av.x + acc[i][1] * av.y + acc[i][2] * av.z + acc[i][3] * av.w;
#pragma unroll
        for (int s = 16; s > 0; s >>= 1) p += __shfl_xor_sync(0xffffffffu, p, s);
        if (tx == 0) atomicAdd(&g_anode[r], p);
    }
}

// ---------------- softmax (fused a_he): one WARP per row of 513 ----------------
// grid 256 blocks x 8 warps = 2048 rows.
__global__ void k_softmax(const float* __restrict__ he) {
    __shared__ float sanm[NM];
    __shared__ float svb[IN_];
    int t = threadIdx.x;
    sanm[t]       = g_anode[ND + t];
    sanm[t + 256] = g_anode[ND + t + 256];
    svb[t] = g_vb[t];
    __syncthreads();
    int w = t >> 5, lane = t & 31;
    int d = blockIdx.x * 8 + w;
    // a_he = he_attr[d] . vb
    const float* hb = he + (size_t)d * IN_;
    float ah = 0.f;
#pragma unroll
    for (int j = 0; j < 8; j++) {
        int i = lane + j * 32;
        ah += hb[i] * svb[i];
    }
#pragma unroll
    for (int s = 16; s > 0; s >>= 1) ah += __shfl_xor_sync(0xffffffffu, ah, s);

    float l[16];
    float mx = -1e30f;
#pragma unroll
    for (int j = 0; j < 16; j++) {
        l[j] = lrelu(sanm[lane + j * 32] + ah);
        mx = fmaxf(mx, l[j]);
    }
    float l0 = lrelu(g_anode[d] + ah);   // broadcast load, same on all lanes
    mx = fmaxf(mx, l0);
#pragma unroll
    for (int s = 16; s > 0; s >>= 1) mx = fmaxf(mx, __shfl_xor_sync(0xffffffffu, mx, s));
    float psum = 0.f;
#pragma unroll
    for (int j = 0; j < 16; j++) {
        l[j] = __expf(l[j] - mx);
        psum += l[j];
    }
#pragma unroll
    for (int s = 16; s > 0; s >>= 1) psum += __shfl_xor_sync(0xffffffffu, psum, s);
    float e0 = __expf(l0 - mx);
    float inv = 1.f / (psum + e0);
#pragma unroll
    for (int j = 0; j < 16; j++)
        g_E[(size_t)d * NM + lane + j * 32] = l[j] * inv;
    if (lane == 0) g_alpha0[d] = e0 * inv;
}

// ---------------- GEMM2: eacc = E @ x_lin_med  (M=2048, N=128, K=512) ----------------
// BM=64, split-K x8 (chunk 64). grid (32, 8) = 256 CTAs.
__global__ void k_gemm2() {
    __shared__ __align__(16) float As[16][68];
    __shared__ __align__(16) float Bs[16][128];
    int t = threadIdx.x;
    int m0 = blockIdx.x * 64;
    int kbase = blockIdx.y * 64;
    int ty = t >> 5, tx = t & 31;
    float acc[8][4] = {};
#pragma unroll
    for (int kt = 0; kt < 4; kt++) {
        int k0 = kbase + kt * 16;
        {   // A tile from E (row-major, stride NM), transpose
            int r = t >> 2, kq = (t & 3) * 4;
            float4 v = *(const float4*)(&g_E[(size_t)(m0 + r) * NM + k0 + kq]);
            As[kq + 0][r] = v.x; As[kq + 1][r] = v.y; As[kq + 2][r] = v.z; As[kq + 3][r] = v.w;
        }
#pragma unroll
        for (int it = 0; it < 2; it++) {   // B tile from x_lin_med (row-major [k][n])
            int k = (t >> 5) + it * 8;
            int n4 = (t & 31) * 4;
            float4 v = *(const float4*)(&g_xlin[(size_t)(ND + k0 + k) * OC + n4]);
            *(float4*)&Bs[k][n4] = v;
        }
        __syncthreads();
        MMA_STEP(As, Bs)
        __syncthreads();
    }
#pragma unroll
    for (int i = 0; i < 8; i++) {
        int r = m0 + ty * 8 + i;
        float* dst = &g_eacc[(size_t)r * OC + tx * 4];
        atomicAdd(dst + 0, acc[i][0]); atomicAdd(dst + 1, acc[i][1]);
        atomicAdd(dst + 2, acc[i][2]); atomicAdd(dst + 3, acc[i][3]);
    }
}

// ---------------- epilogue 1: e, disease output rows ----------------
__global__ void k_epi1(const float* __restrict__ bg, float* __restrict__ out) {
    int idx = blockIdx.x * blockDim.x + threadIdx.x;   // ND*OC threads
    int d = idx >> 7, n = idx & 127;
    float a0 = g_alpha0[d];
    float e  = (a0 * g_xlin[(size_t)d * OC + n] + g_eacc[idx]) * (1.f / NEDG);
    g_e[idx] = e;
    out[(size_t)d * (2 * OC) + n]      = a0 * e + bg[n];
    out[(size_t)d * (2 * OC) + OC + n] = g_convc[n];
}

// ---------------- GEMM3: macc = E^T @ e  (M=512, N=128, K=2048) ----------------
// BM=64, split-K x32 (chunk 64). grid (8, 32) = 256 CTAs.
__global__ void k_gemm3() {
    __shared__ __align__(16) float As[16][68];
    __shared__ __align__(16) float Bs[16][128];
    int t = threadIdx.x;
    int m0 = blockIdx.x * 64;
    int kbase = blockIdx.y * 64;
    int ty = t >> 5, tx = t & 31;
    float acc[8][4] = {};
#pragma unroll
    for (int kt = 0; kt < 4; kt++) {
        int k0 = kbase + kt * 16;
        {   // A = E^T: As[k][m] = E[k0+k][m0+m]; float4 along m, no transpose needed
            int k = t >> 4, mq = (t & 15) * 4;
            float4 v = *(const float4*)(&g_E[(size_t)(k0 + k) * NM + m0 + mq]);
            *(float4*)&As[k][mq] = v;
        }
#pragma unroll
        for (int it = 0; it < 2; it++) {   // B tile from g_e (row-major [k][n])
            int k = (t >> 5) + it * 8;
            int n4 = (t & 31) * 4;
            float4 v = *(const float4*)(&g_e[(size_t)(k0 + k) * OC + n4]);
            *(float4*)&Bs[k][n4] = v;
        }
        __syncthreads();
        MMA_STEP(As, Bs)
        __syncthreads();
    }
#pragma unroll
    for (int i = 0; i < 8; i++) {
        int r = m0 + ty * 8 + i;
        float* dst = &g_macc[(size_t)r * OC + tx * 4];
        atomicAdd(dst + 0, acc[i][0]); atomicAdd(dst + 1, acc[i][1]);
        atomicAdd(dst + 2, acc[i][2]); atomicAdd(dst + 3, acc[i][3]);
    }
}

// ---------------- epilogue 2: medicine output rows ----------------
__global__ void k_epi2(const float* __restrict__ bg, float* __restrict__ out) {
    int idx = blockIdx.x * blockDim.x + threadIdx.x;   // NM*OC threads
    int m = idx >> 7, n = idx & 127;
    out[(size_t)(ND + m) * (2 * OC) + n]      = g_macc[idx] * (1.f / ND) + bg[n];
    out[(size_t)(ND + m) * (2 * OC) + OC + n] = g_convm[n];
}

// ---------------- launch ----------------
extern "C" void kernel_launch(void* const* d_in, const int* in_sizes, int n_in,
                              void* d_out, int out_size) {
    const float* cemb = (const float*)d_in[2];
    const float* memb = (const float*)d_in[3];
    const float* Wc   = (const float*)d_in[4];
    const float* bc   = (const float*)d_in[5];
    const float* Wg   = (const float*)d_in[6];
    const float* att  = (const float*)d_in[7];
    const float* bg   = (const float*)d_in[8];
    const float* he   = (const float*)d_in[9];
    float* out = (float*)d_out;

    k_zero<<<512, 256>>>();
    k_prep<<<81, 256>>>(cemb, memb, Wg, att);
    k_conv<<<1, 256>>>(Wc, bc);
    k_gemm1<<<dim3(NTOT / 64, 4), 256>>>(cemb, memb, Wg, att);
    k_softmax<<<ND / 8, 256>>>(he);
    k_gemm2<<<dim3(ND / 64, 8), 256>>>();
    k_epi1<<<ND * OC / 256, 256>>>(bg, out);
    k_gemm3<<<dim3(NM / 64, 32), 256>>>();
    k_epi2<<<NM * OC / 256, 256>>>(bg, out);
}

// round 8
// speedup vs baseline: 1.7111x; 1.4263x over previous
#include <cuda_runtime.h>
#include <cuda_bf16.h>

// Problem dims (fixed for this problem instance)
#define ND   2048
#define NM   512
#define IN_  256
#define OC   128
#define NTOT (ND + NM)      // 2560
#define NEDG (NM + 1)       // 513
#define NCTA 296            // 2 x 148 SMs; co-residency guaranteed by launch_bounds
#define NTHR 256

// ---------------- device scratch (statically zero-initialized) ----------------
// Atomic accumulation targets are reset by the phase AFTER their last reader,
// so every launch (and every graph replay) starts from zeros.
__device__ float g_xlin[NTOT * OC];
__device__ float g_anode[NTOT];
__device__ float g_E[ND * NM];
__device__ float g_alpha0[ND];
__device__ float g_e[ND * OC];
__device__ float g_eacc[ND * OC];
__device__ float g_macc[NM * OC];
__device__ float g_meanc[IN_];
__device__ float g_meanm[IN_];
__device__ float g_vb[IN_];
__device__ float g_convc[OC];
__device__ float g_convm[OC];
__device__ unsigned g_gen, g_cnt;   // grid barrier state (cnt returns to 0 each barrier)

__device__ __forceinline__ float lrelu(float x) { return x > 0.f ? x : 0.2f * x; }

// ---------------- sense-reversing software grid barrier ----------------
__device__ __forceinline__ void gsync() {
    __syncthreads();
    if (threadIdx.x == 0) {
        __threadfence();
        unsigned my = *(volatile unsigned*)&g_gen;
        if (atomicAdd(&g_cnt, 1u) == NCTA - 1u) {
            atomicExch(&g_cnt, 0u);
            __threadfence();
            atomicAdd(&g_gen, 1u);
        } else {
            while (*(volatile unsigned*)&g_gen == my) __nanosleep(128);
        }
        __threadfence();
    }
    __syncthreads();
}

// ---------------- 8x4 per-thread MMA step over a BK=16 slab ----------------
__device__ __forceinline__ void mma16(const float (*As)[68], const float (*Bs)[128],
                                      float acc[8][4], int ty, int tx) {
#pragma unroll
    for (int kk = 0; kk < 16; kk++) {
        float4 a0 = *(const float4*)&As[kk][ty * 8];
        float4 a1 = *(const float4*)&As[kk][ty * 8 + 4];
        float4 b  = *(const float4*)&Bs[kk][tx * 4];
        acc[0][0] += a0.x * b.x; acc[0][1] += a0.x * b.y; acc[0][2] += a0.x * b.z; acc[0][3] += a0.x * b.w;
        acc[1][0] += a0.y * b.x; acc[1][1] += a0.y * b.y; acc[1][2] += a0.y * b.z; acc[1][3] += a0.y * b.w;
        acc[2][0] += a0.z * b.x; acc[2][1] += a0.z * b.y; acc[2][2] += a0.z * b.z; acc[2][3] += a0.z * b.w;
        acc[3][0] += a0.w * b.x; acc[3][1] += a0.w * b.y; acc[3][2] += a0.w * b.z; acc[3][3] += a0.w * b.w;
        acc[4][0] += a1.x * b.x; acc[4][1] += a1.x * b.y; acc[4][2] += a1.x * b.z; acc[4][3] += a1.x * b.w;
        acc[5][0] += a1.y * b.x; acc[5][1] += a1.y * b.y; acc[5][2] += a1.y * b.z; acc[5][3] += a1.y * b.w;
        acc[6][0] += a1.z * b.x; acc[6][1] += a1.z * b.y; acc[6][2] += a1.z * b.z; acc[6][3] += a1.z * b.w;
        acc[7][0] += a1.w * b.x; acc[7][1] += a1.w * b.y; acc[7][2] += a1.w * b.z; acc[7][3] += a1.w * b.w;
    }
}

__global__ __launch_bounds__(NTHR, 2)
void k_fused(const float* __restrict__ cemb, const float* __restrict__ memb,
             const float* __restrict__ Wc,   const float* __restrict__ bc,
             const float* __restrict__ Wg,   const float* __restrict__ att,
             const float* __restrict__ bg,   const float* __restrict__ he,
             float* __restrict__ out) {
    __shared__ __align__(16) float sA[16 * 68];    // also sanm[512]+svb[256] in softmax phase
    __shared__ __align__(16) float sB[16 * 128];
    __shared__ float sX[OC];

    const int cta = blockIdx.x;
    const int t   = threadIdx.x;
    const int ty  = t >> 5, tx = t & 31;
    const int gid = cta * NTHR + t;
    const int tot = NCTA * NTHR;
    float (*As)[68]  = (float(*)[68])sA;
    float (*Bs)[128] = (float(*)[128])sB;

    // ======== Phase 1: gemm1 (160 tiles) + column sums (80 CTAs) + vb (1 CTA) ========
    if (cta < 160) {
        // x_lin = comb @ Wg^T; BM=64, BN=128, K-chunk 64. mt = cta/4, ks = cta%4.
        int m0 = (cta >> 2) * 64;
        int kbase = (cta & 3) * 64;
        const float* A = (m0 < ND) ? (cemb + (size_t)m0 * IN_) : (memb + (size_t)(m0 - ND) * IN_);
        if (t < OC) sX[t] = att[t];
        float acc[8][4] = {};
#pragma unroll
        for (int kt = 0; kt < 4; kt++) {
            int k0 = kbase + kt * 16;
            {   // A tile: 64 rows x 16 k, transposed
                int r = t >> 2, kq = (t & 3) * 4;
                float4 v = *(const float4*)(A + (size_t)r * IN_ + k0 + kq);
                As[kq + 0][r] = v.x; As[kq + 1][r] = v.y; As[kq + 2][r] = v.z; As[kq + 3][r] = v.w;
            }
            {   // B tile from Wg
                int n = t >> 1, kh = (t & 1) * 8;
                float4 v0 = *(const float4*)(Wg + (size_t)n * IN_ + k0 + kh);
                float4 v1 = *(const float4*)(Wg + (size_t)n * IN_ + k0 + kh + 4);
                Bs[kh + 0][n] = v0.x; Bs[kh + 1][n] = v0.y; Bs[kh + 2][n] = v0.z; Bs[kh + 3][n] = v0.w;
                Bs[kh + 4][n] = v1.x; Bs[kh + 5][n] = v1.y; Bs[kh + 6][n] = v1.z; Bs[kh + 7][n] = v1.w;
            }
            __syncthreads();
            mma16(As, Bs, acc, ty, tx);
            __syncthreads();
        }
        float4 av = *(const float4*)&sX[tx * 4];
#pragma unroll
        for (int i = 0; i < 8; i++) {
            int r = m0 + ty * 8 + i;
            float* dst = &g_xlin[(size_t)r * OC + tx * 4];
            atomicAdd(dst + 0, acc[i][0]); atomicAdd(dst + 1, acc[i][1]);
            atomicAdd(dst + 2, acc[i][2]); atomicAdd(dst + 3, acc[i][3]);
            float p = acc[i][0] * av.x + acc[i][1] * av.y + acc[i][2] * av.z + acc[i][3] * av.w;
#pragma unroll
            for (int s = 16; s > 0; s >>= 1) p += __shfl_xor_sync(0xffffffffu, p, s);
            if (tx == 0) atomicAdd(&g_anode[r], p);
        }
    } else if (cta < 240) {
        int b = cta - 160;                    // 0..79: column sums, 32-row chunks
        const float* base = (b < 64) ? (cemb + (size_t)b * 32 * IN_)
                                     : (memb + (size_t)(b - 64) * 32 * IN_);
        float s = 0.f;
#pragma unroll
        for (int r = 0; r < 32; r++) s += base[r * IN_ + t];
        atomicAdd((b < 64) ? &g_meanc[t] : &g_meanm[t], s);
    } else if (cta == 240) {
        float s = 0.f;                        // vb = Wg^T @ att[OC:]
        for (int o = 0; o < OC; o++) s += Wg[o * IN_ + t] * att[OC + o];
        g_vb[t] = s;
    }
    gsync();

    // ======== Phase 2: softmax (2048 warp-rows) + conv vectors (256 idle warps) ========
    if (cta < 256) {
        sA[t]       = g_anode[ND + t];
        sA[256 + t] = g_anode[ND + 256 + t];
        sA[512 + t] = g_vb[t];
    }
    __syncthreads();
    {
        int w = ty, lane = tx;
        int g = cta * 8 + w;
        if (g < ND) {
            int d = g;
            const float* hb = he + (size_t)d * IN_;
            float ah = 0.f;
#pragma unroll
            for (int j = 0; j < 8; j++) { int i = lane + j * 32; ah += hb[i] * sA[512 + i]; }
#pragma unroll
            for (int s = 16; s > 0; s >>= 1) ah += __shfl_xor_sync(0xffffffffu, ah, s);
            float l[16];
            float mx = -1e30f;
#pragma unroll
            for (int j = 0; j < 16; j++) { l[j] = lrelu(sA[lane + j * 32] + ah); mx = fmaxf(mx, l[j]); }
            float l0 = lrelu(g_anode[d] + ah);
            mx = fmaxf(mx, l0);
#pragma unroll
            for (int s = 16; s > 0; s >>= 1) mx = fmaxf(mx, __shfl_xor_sync(0xffffffffu, mx, s));
            float psum = 0.f;
#pragma unroll
            for (int j = 0; j < 16; j++) { l[j] = __expf(l[j] - mx); psum += l[j]; }
#pragma unroll
            for (int s = 16; s > 0; s >>= 1) psum += __shfl_xor_sync(0xffffffffu, psum, s);
            float e0 = __expf(l0 - mx);
            float inv = 1.f / (psum + e0);
#pragma unroll
            for (int j = 0; j < 16; j++) g_E[(size_t)d * NM + lane + j * 32] = l[j] * inv;
            if (lane == 0) g_alpha0[d] = e0 * inv;
        } else if (g < ND + 128) {
            int o = g - ND;                  // convc channel
            float s = 0.f;
#pragma unroll
            for (int j = 0; j < 8; j++) { int i = lane + j * 32; s += Wc[o * IN_ + i] * g_meanc[i]; }
#pragma unroll
            for (int sh = 16; sh > 0; sh >>= 1) s += __shfl_xor_sync(0xffffffffu, s, sh);
            if (lane == 0) g_convc[o] = s * (1.f / ND) + bc[o];
        } else if (g < ND + 256) {
            int o = g - ND - 128;            // convm channel
            float s = 0.f;
#pragma unroll
            for (int j = 0; j < 8; j++) { int i = lane + j * 32; s += Wc[o * IN_ + i] * g_meanm[i]; }
#pragma unroll
            for (int sh = 16; sh > 0; sh >>= 1) s += __shfl_xor_sync(0xffffffffu, s, sh);
            if (lane == 0) g_convm[o] = s * (1.f / NM) + bc[o];
        }
    }
    gsync();

    // ======== Phase 3: gemm2  eacc = E @ x_lin_med (M=2048,N=128,K=512), 256 tiles ========
    if (cta < 256) {
        int m0 = (cta >> 3) * 64;
        int kbase = (cta & 7) * 64;
        float acc[8][4] = {};
#pragma unroll
        for (int kt = 0; kt < 4; kt++) {
            int k0 = kbase + kt * 16;
            {
                int r = t >> 2, kq = (t & 3) * 4;
                float4 v = *(const float4*)(&g_E[(size_t)(m0 + r) * NM + k0 + kq]);
                As[kq + 0][r] = v.x; As[kq + 1][r] = v.y; As[kq + 2][r] = v.z; As[kq + 3][r] = v.w;
            }
#pragma unroll
            for (int it = 0; it < 2; it++) {
                int k = (t >> 5) + it * 8;
                int n4 = (t & 31) * 4;
                float4 v = *(const float4*)(&g_xlin[(size_t)(ND + k0 + k) * OC + n4]);
                *(float4*)&Bs[k][n4] = v;
            }
            __syncthreads();
            mma16(As, Bs, acc, ty, tx);
            __syncthreads();
        }
#pragma unroll
        for (int i = 0; i < 8; i++) {
            int r = m0 + ty * 8 + i;
            float* dst = &g_eacc[(size_t)r * OC + tx * 4];
            atomicAdd(dst + 0, acc[i][0]); atomicAdd(dst + 1, acc[i][1]);
            atomicAdd(dst + 2, acc[i][2]); atomicAdd(dst + 3, acc[i][3]);
        }
    }
    gsync();

    // ======== Phase 4: epilogue 1 (e + disease rows) + state resets ========
    for (int idx = gid; idx < ND * OC; idx += tot) {
        int d = idx >> 7, n = idx & 127;
        float a0 = g_alpha0[d];
        float e  = (a0 * g_xlin[idx] + g_eacc[idx]) * (1.f / NEDG);
        g_e[idx] = e;
        out[(size_t)d * (2 * OC) + n]      = a0 * e + bg[n];
        out[(size_t)d * (2 * OC) + OC + n] = g_convc[n];
        g_eacc[idx] = 0.f;                 // reset for next replay (last read: here)
        g_xlin[idx] = 0.f;                 // dia rows last read here
    }
    for (int i = gid; i < NM * OC; i += tot) g_xlin[ND * OC + i] = 0.f;  // med rows (last read: P3)
    for (int i = gid; i < NTOT; i += tot) g_anode[i] = 0.f;              // last read: P2
    if (gid < IN_) g_meanc[gid] = 0.f;                                   // last read: P2
    else if (gid < 2 * IN_) g_meanm[gid - IN_] = 0.f;
    gsync();

    // ======== Phase 5: gemm3  macc = E^T @ e (M=512,N=128,K=2048), 256 tiles ========
    if (cta < 256) {
        int m0 = (cta >> 5) * 64;
        int kbase = (cta & 31) * 64;
        float acc[8][4] = {};
#pragma unroll
        for (int kt = 0; kt < 4; kt++) {
            int k0 = kbase + kt * 16;
            {   // A = E^T: As[k][m], float4 along m
                int k = t >> 4, mq = (t & 15) * 4;
                float4 v = *(const float4*)(&g_E[(size_t)(k0 + k) * NM + m0 + mq]);
                *(float4*)&As[k][mq] = v;
            }
#pragma unroll
            for (int it = 0; it < 2; it++) {
                int k = (t >> 5) + it * 8;
                int n4 = (t & 31) * 4;
                float4 v = *(const float4*)(&g_e[(size_t)(k0 + k) * OC + n4]);
                *(float4*)&Bs[k][n4] = v;
            }
            __syncthreads();
            mma16(As, Bs, acc, ty, tx);
            __syncthreads();
        }
#pragma unroll
        for (int i = 0; i < 8; i++) {
            int r = m0 + ty * 8 + i;
            float* dst = &g_macc[(size_t)r * OC + tx * 4];
            atomicAdd(dst + 0, acc[i][0]); atomicAdd(dst + 1, acc[i][1]);
            atomicAdd(dst + 2, acc[i][2]); atomicAdd(dst + 3, acc[i][3]);
        }
    }
    gsync();

    // ======== Phase 6: epilogue 2 (medicine rows) + macc reset ========
    for (int idx = gid; idx < NM * OC; idx += tot) {
        int m = idx >> 7, n = idx & 127;
        out[(size_t)(ND + m) * (2 * OC) + n]      = g_macc[idx] * (1.f / ND) + bg[n];
        out[(size_t)(ND + m) * (2 * OC) + OC + n] = g_convm[n];
        g_macc[idx] = 0.f;
    }
}

// ---------------- launch: ONE kernel ----------------
extern "C" void kernel_launch(void* const* d_in, const int* in_sizes, int n_in,
                              void* d_out, int out_size) {
    const float* cemb = (const float*)d_in[2];
    const float* memb = (const float*)d_in[3];
    const float* Wc   = (const float*)d_in[4];
    const float* bc   = (const float*)d_in[5];
    const float* Wg   = (const float*)d_in[6];
    const float* att  = (const float*)d_in[7];
    const float* bg   = (const float*)d_in[8];
    const float* he   = (const float*)d_in[9];
    float* out = (float*)d_out;

    k_fused<<<NCTA, NTHR>>>(cemb, memb, Wc, bc, Wg, att, bg, he, out);
}

// round 9
// speedup vs baseline: 2.1344x; 1.2474x over previous
#include <cuda_runtime.h>

// Problem dims (fixed)
#define ND   2048
#define NM   512
#define IN_  256
#define OC   128
#define NTOT 2560
#define NEDG 513
#define NCTA 296
#define NTHR 256
#define SAPAD 36      // smem row stride (words): conflict-free STS.128 + LDS.32

// ---------------- device scratch (statically zero-initialized; reset in-kernel) ----------------
__device__ float g_xlin[NTOT * OC];
__device__ float g_anode[NTOT];
__device__ float g_E[ND * NM];
__device__ float g_alpha0[ND];
__device__ float g_e[ND * OC];
__device__ float g_eacc[ND * OC];
__device__ float g_macc[NM * OC];
__device__ float g_meanc[IN_], g_meanm[IN_], g_vb[IN_];
__device__ float g_convc[OC], g_convm[OC];
__device__ unsigned g_gen, g_cnt;

__device__ __forceinline__ float lrelu(float x) { return x > 0.f ? x : 0.2f * x; }
__device__ __forceinline__ float tf32r(float x) { asm("cvt.rna.tf32.f32 %0, %0;" : "+f"(x)); return x; }

// ---------------- sense-reversing software grid barrier ----------------
__device__ __forceinline__ void gsync() {
    __syncthreads();
    if (threadIdx.x == 0) {
        __threadfence();
        unsigned my = *(volatile unsigned*)&g_gen;
        if (atomicAdd(&g_cnt, 1u) == NCTA - 1u) {
            atomicExch(&g_cnt, 0u);
            __threadfence();
            atomicAdd(&g_gen, 1u);
        } else {
            while (*(volatile unsigned*)&g_gen == my) __nanosleep(64);
        }
        __threadfence();
    }
    __syncthreads();
}

// ---------------- m16n8k8 tf32 mma, fp32 accumulate ----------------
// a0=(g,c) a1=(g+8,c) a2=(g,c+4) a3=(g+8,c+4); b0=(k=c,n=g) b1=(k=c+4,n=g)
__device__ __forceinline__ void mma8(float* d, float a0, float a1, float a2, float a3,
                                     float b0, float b1) {
    asm volatile(
        "mma.sync.aligned.m16n8k8.row.col.f32.tf32.tf32.f32 "
        "{%0,%1,%2,%3}, {%4,%5,%6,%7}, {%8,%9}, {%0,%1,%2,%3};"
        : "+f"(d[0]), "+f"(d[1]), "+f"(d[2]), "+f"(d[3])
        : "r"(__float_as_uint(a0)), "r"(__float_as_uint(a1)),
          "r"(__float_as_uint(a2)), "r"(__float_as_uint(a3)),
          "r"(__float_as_uint(b0)), "r"(__float_as_uint(b1)));
}

// Load 64xK32 A tile from row-major (k-contiguous) source. Coalesced LDG.128 + clean STS.128.
#define LOAD_A_ROWK(SRC, LD) do {                                               \
    _Pragma("unroll")                                                           \
    for (int i_ = 0; i_ < 2; i_++) {                                            \
        int idx_ = t * 2 + i_; int m_ = idx_ >> 3; int o4_ = (idx_ & 7) * 4;    \
        float4 v_ = *(const float4*)((SRC) + (size_t)m_ * (LD) + o4_);          \
        sA[m_][o4_ + 0] = tf32r(v_.x); sA[m_][o4_ + 1] = tf32r(v_.y);           \
        sA[m_][o4_ + 2] = tf32r(v_.z); sA[m_][o4_ + 3] = tf32r(v_.w);           \
    } } while (0)

// Load 128xK32 B tile from row-major [n][k] (k-contiguous) source.
#define LOAD_B_ROWK(SRC, LD) do {                                               \
    _Pragma("unroll")                                                           \
    for (int i_ = 0; i_ < 4; i_++) {                                            \
        int idx_ = i_ * 256 + t; int n_ = idx_ >> 3; int o4_ = (idx_ & 7) * 4;  \
        float4 v_ = *(const float4*)((SRC) + (size_t)n_ * (LD) + o4_);          \
        sB[n_][o4_ + 0] = tf32r(v_.x); sB[n_][o4_ + 1] = tf32r(v_.y);           \
        sB[n_][o4_ + 2] = tf32r(v_.z); sB[n_][o4_ + 3] = tf32r(v_.w);           \
    } } while (0)

// Load K32x128 B tile from [k][n] (n-contiguous) source. k = lane -> conflict-free STS.
#define LOAD_B_KN(SRC) do {                                                     \
    _Pragma("unroll")                                                           \
    for (int i_ = 0; i_ < 4; i_++) {                                            \
        int idx_ = i_ * 256 + t; int k_ = idx_ & 31; int n4_ = (idx_ >> 5) * 4; \
        float4 v_ = *(const float4*)((SRC) + (size_t)k_ * OC + n4_);            \
        sB[n4_ + 0][k_] = tf32r(v_.x); sB[n4_ + 1][k_] = tf32r(v_.y);           \
        sB[n4_ + 2][k_] = tf32r(v_.z); sB[n4_ + 3][k_] = tf32r(v_.w);           \
    } } while (0)

// 4 k-steps of mma over the 32-k subchunk: warp tile 32(m) x 32(n)
#define MMA_SUB(ACC) do {                                                       \
    _Pragma("unroll")                                                           \
    for (int ks_ = 0; ks_ < 4; ks_++) {                                         \
        int kc_ = ks_ * 8 + c;                                                  \
        float a0_ = sA[m0w + g     ][kc_], a0h_ = sA[m0w + g     ][kc_ + 4];    \
        float a1_ = sA[m0w + g +  8][kc_], a1h_ = sA[m0w + g +  8][kc_ + 4];    \
        float a2_ = sA[m0w + g + 16][kc_], a2h_ = sA[m0w + g + 16][kc_ + 4];    \
        float a3_ = sA[m0w + g + 24][kc_], a3h_ = sA[m0w + g + 24][kc_ + 4];    \
        _Pragma("unroll")                                                       \
        for (int ni_ = 0; ni_ < 4; ni_++) {                                     \
            float bx_ = sB[n0w + ni_ * 8 + g][kc_];                             \
            float by_ = sB[n0w + ni_ * 8 + g][kc_ + 4];                         \
            mma8(ACC[0][ni_], a0_, a1_, a0h_, a1h_, bx_, by_);                  \
            mma8(ACC[1][ni_], a2_, a3_, a2h_, a3h_, bx_, by_);                  \
        }                                                                       \
    } } while (0)

// Flush warp accumulators to DST[r][col] via split-K atomics
#define FLUSH(DST, M0) do {                                                     \
    _Pragma("unroll")                                                           \
    for (int mi_ = 0; mi_ < 2; mi_++) {                                         \
        int r0_ = (M0) + m0w + mi_ * 16 + g;                                    \
        _Pragma("unroll")                                                       \
        for (int ni_ = 0; ni_ < 4; ni_++) {                                     \
            int col_ = n0w + ni_ * 8 + 2 * c;                                   \
            float* d0_ = &(DST)[(size_t)r0_ * OC + col_];                       \
            atomicAdd(d0_ + 0, acc[mi_][ni_][0]);                               \
            atomicAdd(d0_ + 1, acc[mi_][ni_][1]);                               \
            float* d8_ = &(DST)[(size_t)(r0_ + 8) * OC + col_];                 \
            atomicAdd(d8_ + 0, acc[mi_][ni_][2]);                               \
            atomicAdd(d8_ + 1, acc[mi_][ni_][3]);                               \
        }                                                                       \
    } } while (0)

__global__ __launch_bounds__(NTHR, 2)
void k_fused(const float* __restrict__ cemb, const float* __restrict__ memb,
             const float* __restrict__ Wc,   const float* __restrict__ bc,
             const float* __restrict__ Wg,   const float* __restrict__ att,
             const float* __restrict__ bg,   const float* __restrict__ he,
             float* __restrict__ out) {
    __shared__ __align__(16) float sA[64][SAPAD];     // 9216 B (reused as scratch in softmax)
    __shared__ __align__(16) float sB[128][SAPAD];    // 18432 B
    __shared__ float sX[OC];

    const int cta = blockIdx.x;
    const int t   = threadIdx.x;
    const int w   = t >> 5, lane = t & 31;
    const int g   = lane >> 2, c = lane & 3;
    const int m0w = (w & 1) * 32;     // warp m-offset within 64-row CTA tile
    const int n0w = (w >> 1) * 32;    // warp n-offset within 128-col CTA tile
    const int gid = cta * NTHR + t;
    const int tot = NCTA * NTHR;

    // ======== Phase 1: gemm1 (160 items) + column sums (80 CTAs) + vb (1 CTA) ========
    if (cta < 160) {
        // x_lin = comb @ Wg^T; M-tile 64, ksplit 4 (chunk 64 = 2 subchunks of 32)
        if (t < OC) sX[t] = att[t];
        int m0 = (cta >> 2) * 64;
        int kb = (cta & 3) * 64;
        const float* Ab = (m0 < ND) ? cemb + (size_t)m0 * IN_ : memb + (size_t)(m0 - ND) * IN_;
        float acc[2][4][4] = {};
        for (int sub = 0; sub < 2; sub++) {
            int k0 = kb + sub * 32;
            LOAD_A_ROWK(Ab + k0, IN_);
            LOAD_B_ROWK(Wg + k0, IN_);
            __syncthreads();
            MMA_SUB(acc);
            __syncthreads();
        }
        // flush x_lin + fused partial a_node (per-warp 32-col partial dot)
#pragma unroll
        for (int mi = 0; mi < 2; mi++) {
            int r0 = m0 + m0w + mi * 16 + g;
            float an0 = 0.f, an8 = 0.f;
#pragma unroll
            for (int ni = 0; ni < 4; ni++) {
                int col = n0w + ni * 8 + 2 * c;
                float* d0 = &g_xlin[(size_t)r0 * OC + col];
                atomicAdd(d0 + 0, acc[mi][ni][0]); atomicAdd(d0 + 1, acc[mi][ni][1]);
                float* d8 = &g_xlin[(size_t)(r0 + 8) * OC + col];
                atomicAdd(d8 + 0, acc[mi][ni][2]); atomicAdd(d8 + 1, acc[mi][ni][3]);
                an0 += acc[mi][ni][0] * sX[col] + acc[mi][ni][1] * sX[col + 1];
                an8 += acc[mi][ni][2] * sX[col] + acc[mi][ni][3] * sX[col + 1];
            }
            an0 += __shfl_xor_sync(0xffffffffu, an0, 1);
            an0 += __shfl_xor_sync(0xffffffffu, an0, 2);
            an8 += __shfl_xor_sync(0xffffffffu, an8, 1);
            an8 += __shfl_xor_sync(0xffffffffu, an8, 2);
            if (c == 0) { atomicAdd(&g_anode[r0], an0); atomicAdd(&g_anode[r0 + 8], an8); }
        }
    } else if (cta < 240) {
        int b = cta - 160;
        const float* base = (b < 64) ? (cemb + (size_t)b * 32 * IN_)
                                     : (memb + (size_t)(b - 64) * 32 * IN_);
        float s = 0.f;
#pragma unroll
        for (int r = 0; r < 32; r++) s += base[r * IN_ + t];
        atomicAdd((b < 64) ? &g_meanc[t] : &g_meanm[t], s);
    } else if (cta == 240) {
        float s = 0.f;
        for (int o = 0; o < OC; o++) s += Wg[o * IN_ + t] * att[OC + o];
        g_vb[t] = s;
    }
    gsync();

    // ======== Phase 2: softmax (2048 warp-rows) + conv vectors (idle warps) ========
    {
        float* sf = &sA[0][0];          // sanm[512], svb[256]
        if (cta < 256) {
            sf[t]       = g_anode[ND + t];
            sf[256 + t] = g_anode[ND + 256 + t];
            sf[512 + t] = g_vb[t];
        }
        __syncthreads();
        int gg = cta * 8 + w;
        if (cta < 256 && gg < ND) {
            int d = gg;
            const float* hb = he + (size_t)d * IN_;
            float ah = 0.f;
#pragma unroll
            for (int j = 0; j < 8; j++) { int i = lane + j * 32; ah += hb[i] * sf[512 + i]; }
#pragma unroll
            for (int s = 16; s > 0; s >>= 1) ah += __shfl_xor_sync(0xffffffffu, ah, s);
            float l[16];
            float mx = -1e30f;
#pragma unroll
            for (int j = 0; j < 16; j++) { l[j] = lrelu(sf[lane + j * 32] + ah); mx = fmaxf(mx, l[j]); }
            float l0 = lrelu(g_anode[d] + ah);
            mx = fmaxf(mx, l0);
#pragma unroll
            for (int s = 16; s > 0; s >>= 1) mx = fmaxf(mx, __shfl_xor_sync(0xffffffffu, mx, s));
            float psum = 0.f;
#pragma unroll
            for (int j = 0; j < 16; j++) { l[j] = __expf(l[j] - mx); psum += l[j]; }
#pragma unroll
            for (int s = 16; s > 0; s >>= 1) psum += __shfl_xor_sync(0xffffffffu, psum, s);
            float e0 = __expf(l0 - mx);
            float inv = 1.f / (psum + e0);
#pragma unroll
            for (int j = 0; j < 16; j++) g_E[(size_t)d * NM + lane + j * 32] = l[j] * inv;
            if (lane == 0) g_alpha0[d] = e0 * inv;
        } else if (cta >= 256 && cta < 288) {
            int gi = (cta - 256) * 8 + w;   // 0..255 channels: 0-127 convc, 128-255 convm
            int o = gi & 127;
            const float* mean = (gi < 128) ? g_meanc : g_meanm;
            float s = 0.f;
#pragma unroll
            for (int j = 0; j < 8; j++) { int i = lane + j * 32; s += Wc[o * IN_ + i] * mean[i]; }
#pragma unroll
            for (int sh = 16; sh > 0; sh >>= 1) s += __shfl_xor_sync(0xffffffffu, s, sh);
            if (lane == 0) {
                if (gi < 128) g_convc[o] = s * (1.f / ND) + bc[o];
                else          g_convm[o] = s * (1.f / NM) + bc[o];
            }
        }
    }
    gsync();

    // ======== Phase 3: gemm2  eacc = E @ x_lin_med (M=2048,N=128,K=512), 256 items ========
    if (cta < 256) {
        int m0 = (cta >> 3) * 64;
        int kb = (cta & 7) * 64;
        float acc[2][4][4] = {};
        for (int sub = 0; sub < 2; sub++) {
            int k0 = kb + sub * 32;
            LOAD_A_ROWK(g_E + (size_t)m0 * NM + k0, NM);
            LOAD_B_KN(g_xlin + (size_t)ND * OC + (size_t)k0 * OC);
            __syncthreads();
            MMA_SUB(acc);
            __syncthreads();
        }
        FLUSH(g_eacc, m0);
    }
    gsync();

    // ======== Phase 4: epilogue 1 (e + disease rows) + state resets ========
    for (int idx = gid; idx < ND * OC; idx += tot) {
        int d = idx >> 7, n = idx & 127;
        float a0 = g_alpha0[d];
        float e  = (a0 * g_xlin[idx] + g_eacc[idx]) * (1.f / NEDG);
        g_e[idx] = e;
        out[(size_t)d * (2 * OC) + n]      = a0 * e + bg[n];
        out[(size_t)d * (2 * OC) + OC + n] = g_convc[n];
        g_eacc[idx] = 0.f;
        g_xlin[idx] = 0.f;
    }
    for (int i = gid; i < NM * OC; i += tot) g_xlin[ND * OC + i] = 0.f;
    for (int i = gid; i < NTOT; i += tot) g_anode[i] = 0.f;
    if (gid < IN_) g_meanc[gid] = 0.f;
    else if (gid < 2 * IN_) g_meanm[gid - IN_] = 0.f;
    gsync();

    // ======== Phase 5: gemm3  macc = E^T @ e (M=512,N=128,K=2048), 256 items ========
    if (cta < 256) {
        int m0 = (cta >> 5) * 64;
        int kb = (cta & 31) * 64;
        float acc[2][4][4] = {};
        for (int sub = 0; sub < 2; sub++) {
            int k0 = kb + sub * 32;
            // A = E^T: sA[m][k] = E[k0+k][m0+m]; m-contiguous global, k = lane
#pragma unroll
            for (int i = 0; i < 2; i++) {
                int idx = i * 256 + t; int k = idx & 31; int m4 = (idx >> 5) * 4;
                float4 v = *(const float4*)(&g_E[(size_t)(k0 + k) * NM + m0 + m4]);
                sA[m4 + 0][k] = tf32r(v.x); sA[m4 + 1][k] = tf32r(v.y);
                sA[m4 + 2][k] = tf32r(v.z); sA[m4 + 3][k] = tf32r(v.w);
            }
            LOAD_B_KN(g_e + (size_t)k0 * OC);
            __syncthreads();
            MMA_SUB(acc);
            __syncthreads();
        }
        FLUSH(g_macc, m0);
    }
    gsync();

    // ======== Phase 6: epilogue 2 (medicine rows) + macc reset ========
    for (int idx = gid; idx < NM * OC; idx += tot) {
        int m = idx >> 7, n = idx & 127;
        out[(size_t)(ND + m) * (2 * OC) + n]      = g_macc[idx] * (1.f / ND) + bg[n];
        out[(size_t)(ND + m) * (2 * OC) + OC + n] = g_convm[n];
        g_macc[idx] = 0.f;
    }
}

// ---------------- launch: ONE kernel ----------------
extern "C" void kernel_launch(void* const* d_in, const int* in_sizes, int n_in,
                              void* d_out, int out_size) {
    const float* cemb = (const float*)d_in[2];
    const float* memb = (const float*)d_in[3];
    const float* Wc   = (const float*)d_in[4];
    const float* bc   = (const float*)d_in[5];
    const float* Wg   = (const float*)d_in[6];
    const float* att  = (const float*)d_in[7];
    const float* bg   = (const float*)d_in[8];
    const float* he   = (const float*)d_in[9];
    float* out = (float*)d_out;

    k_fused<<<NCTA, NTHR>>>(cemb, memb, Wc, bc, Wg, att, bg, he, out);
}

// round 10
// speedup vs baseline: 2.2576x; 1.0577x over previous
#include <cuda_runtime.h>

// Problem dims (fixed)
#define ND   2048
#define NM   512
#define IN_  256
#define OC   128
#define NTOT 2560
#define NEDG 513
#define NCTA 296
#define NTHR 256
#define SAPAD 36
#define NDOC (ND * OC)
#define NMOC (NM * OC)

// ---------------- device scratch (all plain stores; only means need resets) ----------------
__device__ float g_xlin[NTOT * OC];
__device__ float g_anode[NTOT];
__device__ float g_E[ND * NM];
__device__ float g_alpha0[ND];
__device__ float g_e[NDOC];
__device__ float g_p2[4 * NDOC];        // gemm2 split-K partials (4 MB)
__device__ float g_p3[16 * NMOC];       // gemm3 split-K partials (4 MB)
__device__ float g_meanc[IN_], g_meanm[IN_], g_vb[IN_];
__device__ float g_convc[OC], g_convm[OC];
__device__ unsigned g_gen, g_cnt;

__device__ __forceinline__ float lrelu(float x) { return x > 0.f ? x : 0.2f * x; }
__device__ __forceinline__ float tf32r(float x) { asm("cvt.rna.tf32.f32 %0, %0;" : "+f"(x)); return x; }

// ---------------- sense-reversing software grid barrier ----------------
__device__ __forceinline__ void gsync() {
    __syncthreads();
    if (threadIdx.x == 0) {
        __threadfence();
        unsigned my = *(volatile unsigned*)&g_gen;
        if (atomicAdd(&g_cnt, 1u) == NCTA - 1u) {
            atomicExch(&g_cnt, 0u);
            __threadfence();
            atomicAdd(&g_gen, 1u);
        } else {
            while (*(volatile unsigned*)&g_gen == my) __nanosleep(64);
        }
        __threadfence();
    }
    __syncthreads();
}

// ---------------- m16n8k8 tf32 mma, fp32 accumulate ----------------
__device__ __forceinline__ void mma8(float* d, float a0, float a1, float a2, float a3,
                                     float b0, float b1) {
    asm volatile(
        "mma.sync.aligned.m16n8k8.row.col.f32.tf32.tf32.f32 "
        "{%0,%1,%2,%3}, {%4,%5,%6,%7}, {%8,%9}, {%0,%1,%2,%3};"
        : "+f"(d[0]), "+f"(d[1]), "+f"(d[2]), "+f"(d[3])
        : "r"(__float_as_uint(a0)), "r"(__float_as_uint(a1)),
          "r"(__float_as_uint(a2)), "r"(__float_as_uint(a3)),
          "r"(__float_as_uint(b0)), "r"(__float_as_uint(b1)));
}

// Load 32xK32 A tile from row-major (k-contiguous) source into sA[m][k].
#define LOAD_A32_ROWK(SRC, LD) do {                                             \
    int m_ = t >> 3, o4_ = (t & 7) * 4;                                         \
    float4 v_ = *(const float4*)((SRC) + (size_t)m_ * (LD) + o4_);              \
    sA[m_][o4_ + 0] = tf32r(v_.x); sA[m_][o4_ + 1] = tf32r(v_.y);               \
    sA[m_][o4_ + 2] = tf32r(v_.z); sA[m_][o4_ + 3] = tf32r(v_.w);               \
    } while (0)

// Load 128xK32 B tile from row-major [n][k] (k-contiguous) source.
#define LOAD_B_ROWK(SRC, LD) do {                                               \
    _Pragma("unroll")                                                           \
    for (int i_ = 0; i_ < 4; i_++) {                                            \
        int idx_ = i_ * 256 + t; int n_ = idx_ >> 3; int o4_ = (idx_ & 7) * 4;  \
        float4 v_ = *(const float4*)((SRC) + (size_t)n_ * (LD) + o4_);          \
        sB[n_][o4_ + 0] = tf32r(v_.x); sB[n_][o4_ + 1] = tf32r(v_.y);           \
        sB[n_][o4_ + 2] = tf32r(v_.z); sB[n_][o4_ + 3] = tf32r(v_.w);           \
    } } while (0)

// Load K32x128 B tile from [k][n] (n-contiguous) source. k = lane -> conflict-free STS.
#define LOAD_B_KN(SRC) do {                                                     \
    _Pragma("unroll")                                                           \
    for (int i_ = 0; i_ < 4; i_++) {                                            \
        int idx_ = i_ * 256 + t; int k_ = idx_ & 31; int n4_ = (idx_ >> 5) * 4; \
        float4 v_ = *(const float4*)((SRC) + (size_t)k_ * OC + n4_);            \
        sB[n4_ + 0][k_] = tf32r(v_.x); sB[n4_ + 1][k_] = tf32r(v_.y);           \
        sB[n4_ + 2][k_] = tf32r(v_.z); sB[n4_ + 3][k_] = tf32r(v_.w);           \
    } } while (0)

// Warp tile m16 x n32 over a 32-k subchunk (for gemm2/gemm3; m0w, n0w set per phase)
#define MMA_M16N32(ACC) do {                                                    \
    _Pragma("unroll")                                                           \
    for (int ks_ = 0; ks_ < 4; ks_++) {                                         \
        int kc_ = ks_ * 8 + c;                                                  \
        float a0_ = sA[m0w + g    ][kc_], a0h_ = sA[m0w + g    ][kc_ + 4];      \
        float a1_ = sA[m0w + g + 8][kc_], a1h_ = sA[m0w + g + 8][kc_ + 4];      \
        _Pragma("unroll")                                                       \
        for (int ni_ = 0; ni_ < 4; ni_++) {                                     \
            float bx_ = sB[n0w + ni_ * 8 + g][kc_];                             \
            float by_ = sB[n0w + ni_ * 8 + g][kc_ + 4];                         \
            mma8(ACC[ni_], a0_, a1_, a0h_, a1h_, bx_, by_);                     \
        }                                                                       \
    } } while (0)

// Direct (non-atomic) flush of m16n32 warp tile to DST[r][col]
#define STORE_M16N32(DST, M0) do {                                              \
    int r0_ = (M0) + m0w + g;                                                   \
    _Pragma("unroll")                                                           \
    for (int ni_ = 0; ni_ < 4; ni_++) {                                         \
        int col_ = n0w + ni_ * 8 + 2 * c;                                       \
        *(float2*)&(DST)[(size_t)r0_ * OC + col_] =                             \
            make_float2(acc[ni_][0], acc[ni_][1]);                              \
        *(float2*)&(DST)[(size_t)(r0_ + 8) * OC + col_] =                       \
            make_float2(acc[ni_][2], acc[ni_][3]);                              \
    } } while (0)

__global__ __launch_bounds__(NTHR, 2)
void k_fused(const float* __restrict__ cemb, const float* __restrict__ memb,
             const float* __restrict__ Wc,   const float* __restrict__ bc,
             const float* __restrict__ Wg,   const float* __restrict__ att,
             const float* __restrict__ bg,   const float* __restrict__ he,
             float* __restrict__ out) {
    __shared__ __align__(16) float sA[32][SAPAD];     // also softmax scratch (1152 floats)
    __shared__ __align__(16) float sB[128][SAPAD];
    __shared__ float sX[OC];
    __shared__ float s_an[16];

    const int cta = blockIdx.x;
    const int t   = threadIdx.x;
    const int w   = t >> 5, lane = t & 31;
    const int g   = lane >> 2, c = lane & 3;
    const int m0w = (w & 1) * 16;     // gemm2/3 warp m-offset (CTA tile 32)
    const int n0w = (w >> 1) * 32;    // gemm2/3 warp n-offset
    const int gid = cta * NTHR + t;
    const int tot = NCTA * NTHR;

    // ======== Phase 1: gemm1 (160 CTAs, full-K, atomic-free) + colsums + vb ========
    if (cta < 160) {
        // x_lin[m0..m0+16] = comb @ Wg^T; CTA tile 16x128, K=256 (8 subchunks)
        int m0 = cta * 16;
        const float* Ab = (m0 < ND) ? cemb + (size_t)m0 * IN_ : memb + (size_t)(m0 - ND) * IN_;
        if (t < OC) sX[t] = att[t];
        if (t < 16) s_an[t] = 0.f;
        const int nw = w * 16;                 // warp tile m16 x n16
        float acc[2][4] = {};
        for (int sub = 0; sub < 8; sub++) {
            int k0 = sub * 32;
            if (t < 128) {                     // A tile 16x32
                int m = t >> 3, o4 = (t & 7) * 4;
                float4 v = *(const float4*)(Ab + (size_t)m * IN_ + k0 + o4);
                sA[m][o4 + 0] = tf32r(v.x); sA[m][o4 + 1] = tf32r(v.y);
                sA[m][o4 + 2] = tf32r(v.z); sA[m][o4 + 3] = tf32r(v.w);
            }
            LOAD_B_ROWK(Wg + k0, IN_);
            __syncthreads();
#pragma unroll
            for (int ks = 0; ks < 4; ks++) {
                int kc = ks * 8 + c;
                float a0 = sA[g][kc],     a0h = sA[g][kc + 4];
                float a1 = sA[g + 8][kc], a1h = sA[g + 8][kc + 4];
#pragma unroll
                for (int ni = 0; ni < 2; ni++) {
                    float bx = sB[nw + ni * 8 + g][kc];
                    float by = sB[nw + ni * 8 + g][kc + 4];
                    mma8(acc[ni], a0, a1, a0h, a1h, bx, by);
                }
            }
            __syncthreads();
        }
        // direct store x_lin + fused a_node (smem reduce, direct store)
        float an0 = 0.f, an8 = 0.f;
#pragma unroll
        for (int ni = 0; ni < 2; ni++) {
            int col = nw + ni * 8 + 2 * c;
            *(float2*)&g_xlin[(size_t)(m0 + g) * OC + col]     = make_float2(acc[ni][0], acc[ni][1]);
            *(float2*)&g_xlin[(size_t)(m0 + g + 8) * OC + col] = make_float2(acc[ni][2], acc[ni][3]);
            an0 += acc[ni][0] * sX[col] + acc[ni][1] * sX[col + 1];
            an8 += acc[ni][2] * sX[col] + acc[ni][3] * sX[col + 1];
        }
        an0 += __shfl_xor_sync(0xffffffffu, an0, 1);
        an0 += __shfl_xor_sync(0xffffffffu, an0, 2);
        an8 += __shfl_xor_sync(0xffffffffu, an8, 1);
        an8 += __shfl_xor_sync(0xffffffffu, an8, 2);
        if (c == 0) { atomicAdd(&s_an[g], an0); atomicAdd(&s_an[g + 8], an8); }
        __syncthreads();
        if (t < 16) g_anode[m0 + t] = s_an[t];
    } else if (cta < 240) {
        int b = cta - 160;
        const float* base = (b < 64) ? (cemb + (size_t)b * 32 * IN_)
                                     : (memb + (size_t)(b - 64) * 32 * IN_);
        float s = 0.f;
#pragma unroll
        for (int r = 0; r < 32; r++) s += base[r * IN_ + t];
        atomicAdd((b < 64) ? &g_meanc[t] : &g_meanm[t], s);
    } else if (cta == 240) {
        float s = 0.f;
        for (int o = 0; o < OC; o++) s += Wg[o * IN_ + t] * att[OC + o];
        g_vb[t] = s;
    }
    gsync();

    // ======== Phase 2: softmax (2048 warp-rows) + conv vectors ========
    {
        float* sf = &sA[0][0];          // sanm[512] + svb[256] = 768 <= 1152
        if (cta < 256) {
            sf[t]       = g_anode[ND + t];
            sf[256 + t] = g_anode[ND + 256 + t];
            sf[512 + t] = g_vb[t];
        }
        __syncthreads();
        int gg = cta * 8 + w;
        if (cta < 256) {
            int d = gg;
            const float* hb = he + (size_t)d * IN_;
            float ah = 0.f;
#pragma unroll
            for (int j = 0; j < 8; j++) { int i = lane + j * 32; ah += hb[i] * sf[512 + i]; }
#pragma unroll
            for (int s = 16; s > 0; s >>= 1) ah += __shfl_xor_sync(0xffffffffu, ah, s);
            float l[16];
            float mx = -1e30f;
#pragma unroll
            for (int j = 0; j < 16; j++) { l[j] = lrelu(sf[lane + j * 32] + ah); mx = fmaxf(mx, l[j]); }
            float l0 = lrelu(g_anode[d] + ah);
            mx = fmaxf(mx, l0);
#pragma unroll
            for (int s = 16; s > 0; s >>= 1) mx = fmaxf(mx, __shfl_xor_sync(0xffffffffu, mx, s));
            float psum = 0.f;
#pragma unroll
            for (int j = 0; j < 16; j++) { l[j] = __expf(l[j] - mx); psum += l[j]; }
#pragma unroll
            for (int s = 16; s > 0; s >>= 1) psum += __shfl_xor_sync(0xffffffffu, psum, s);
            float e0 = __expf(l0 - mx);
            float inv = 1.f / (psum + e0);
#pragma unroll
            for (int j = 0; j < 16; j++) g_E[(size_t)d * NM + lane + j * 32] = l[j] * inv;
            if (lane == 0) g_alpha0[d] = e0 * inv;
        } else if (cta < 288) {
            int gi = (cta - 256) * 8 + w;   // 0-127 convc, 128-255 convm
            int o = gi & 127;
            const float* mean = (gi < 128) ? g_meanc : g_meanm;
            float s = 0.f;
#pragma unroll
            for (int j = 0; j < 8; j++) { int i = lane + j * 32; s += Wc[o * IN_ + i] * mean[i]; }
#pragma unroll
            for (int sh = 16; sh > 0; sh >>= 1) s += __shfl_xor_sync(0xffffffffu, s, sh);
            if (lane == 0) {
                if (gi < 128) g_convc[o] = s * (1.f / ND) + bc[o];
                else          g_convm[o] = s * (1.f / NM) + bc[o];
            }
        }
    }
    gsync();

    // ======== Phase 3: gemm2 partials  p2[s] = E[:,ks] @ xlin_med[ks,:]  (256 CTAs) ========
    if (cta < 256) {
        int m0 = (cta >> 2) * 32;          // 64 m-tiles of 32
        int s  = cta & 3;                  // ksplit 4, chunk 128
        int kb = s * 128;
        float acc[4][4] = {};
        for (int sub = 0; sub < 4; sub++) {
            int k0 = kb + sub * 32;
            LOAD_A32_ROWK(g_E + (size_t)m0 * NM + k0, NM);
            LOAD_B_KN(g_xlin + (size_t)ND * OC + (size_t)k0 * OC);
            __syncthreads();
            MMA_M16N32(acc);
            __syncthreads();
        }
        float* dst = g_p2 + (size_t)s * NDOC;
        STORE_M16N32(dst, m0);
    }
    gsync();

    // ======== Phase 4: epilogue 1 (sum partials -> e, disease rows) + mean resets ========
    for (int idx = gid; idx < NDOC; idx += tot) {
        int d = idx >> 7, n = idx & 127;
        float p = g_p2[idx] + g_p2[NDOC + idx] + g_p2[2 * NDOC + idx] + g_p2[3 * NDOC + idx];
        float a0 = g_alpha0[d];
        float e  = (a0 * g_xlin[idx] + p) * (1.f / NEDG);
        g_e[idx] = e;
        out[(size_t)d * (2 * OC) + n]      = a0 * e + bg[n];
        out[(size_t)d * (2 * OC) + OC + n] = g_convc[n];
    }
    if (gid < IN_) g_meanc[gid] = 0.f;
    else if (gid < 2 * IN_) g_meanm[gid - IN_] = 0.f;
    gsync();

    // ======== Phase 5: gemm3 partials  p3[s] = E^T[:,ks] @ e[ks,:]  (256 CTAs) ========
    if (cta < 256) {
        int m0 = (cta >> 4) * 32;          // 16 m-tiles of 32
        int s  = cta & 15;                 // ksplit 16, chunk 128
        int kb = s * 128;
        float acc[4][4] = {};
        for (int sub = 0; sub < 4; sub++) {
            int k0 = kb + sub * 32;
            {   // A = E^T tile: sA[m][k] = E[k0+k][m0+m]; k = lane -> conflict-free STS
                int k = t & 31, m4 = (t >> 5) * 4;
                float4 v = *(const float4*)(&g_E[(size_t)(k0 + k) * NM + m0 + m4]);
                sA[m4 + 0][k] = tf32r(v.x); sA[m4 + 1][k] = tf32r(v.y);
                sA[m4 + 2][k] = tf32r(v.z); sA[m4 + 3][k] = tf32r(v.w);
            }
            LOAD_B_KN(g_e + (size_t)k0 * OC);
            __syncthreads();
            MMA_M16N32(acc);
            __syncthreads();
        }
        float* dst = g_p3 + (size_t)s * NMOC;
        STORE_M16N32(dst, m0);
    }
    gsync();

    // ======== Phase 6: epilogue 2 (sum 16 partials -> medicine rows) ========
    for (int idx = gid; idx < NMOC; idx += tot) {
        int m = idx >> 7, n = idx & 127;
        float s = 0.f;
#pragma unroll
        for (int si = 0; si < 16; si++) s += g_p3[(size_t)si * NMOC + idx];
        out[(size_t)(ND + m) * (2 * OC) + n]      = s * (1.f / ND) + bg[n];
        out[(size_t)(ND + m) * (2 * OC) + OC + n] = g_convm[n];
    }
}

// ---------------- launch: ONE kernel ----------------
extern "C" void kernel_launch(void* const* d_in, const int* in_sizes, int n_in,
                              void* d_out, int out_size) {
    const float* cemb = (const float*)d_in[2];
    const float* memb = (const float*)d_in[3];
    const float* Wc   = (const float*)d_in[4];
    const float* bc   = (const float*)d_in[5];
    const float* Wg   = (const float*)d_in[6];
    const float* att  = (const float*)d_in[7];
    const float* bg   = (const float*)d_in[8];
    const float* he   = (const float*)d_in[9];
    float* out = (float*)d_out;

    k_fused<<<NCTA, NTHR>>>(cemb, memb, Wc, bc, Wg, att, bg, he, out);
}

// round 11
// speedup vs baseline: 2.8094x; 1.2444x over previous
#include <cuda_runtime.h>

// Problem dims (fixed)
#define ND   2048
#define NM   512
#define IN_  256
#define OC   128
#define NTOT 2560
#define NEDG 513
#define NCTA 296
#define NTHR 256
#define NDOC (ND * OC)
#define NMOC (NM * OC)

// smem layout strides (words), chosen for conflict-free STS.128 + fragment LDS
#define P_AM 36     // row-major A: sAm[m][k]
#define P_BN 36     // row-major B: sBn[n][k]
#define P_KB 136    // k-major B:   sKB[k][n]  (8c+g bank pattern)
#define P_KA 40     // k-major A:   sKA[k][m]

// ---------------- device scratch ----------------
__device__ float g_xlin[NTOT * OC];
__device__ float g_anode[NTOT];
__device__ float g_E[ND * NM];
__device__ float g_alpha0[ND];
__device__ float g_e[NDOC];
__device__ float g_p2[4 * NDOC];        // gemm2 split-K partials
__device__ float g_p3[16 * NMOC];       // gemm3 split-K partials
__device__ float g_meanc[IN_], g_meanm[IN_], g_vb[IN_];
__device__ float g_convc[OC], g_convm[OC];
__device__ unsigned g_gen, g_cnt;

__device__ __forceinline__ float lrelu(float x) { return x > 0.f ? x : 0.2f * x; }
__device__ __forceinline__ float tf32r(float x) { asm("cvt.rna.tf32.f32 %0, %0;" : "+f"(x)); return x; }
__device__ __forceinline__ float4 tf4(float4 v) {
    return make_float4(tf32r(v.x), tf32r(v.y), tf32r(v.z), tf32r(v.w));
}

// ---------------- sense-reversing software grid barrier ----------------
__device__ __forceinline__ void gsync() {
    __syncthreads();
    if (threadIdx.x == 0) {
        __threadfence();
        unsigned my = *(volatile unsigned*)&g_gen;
        if (atomicAdd(&g_cnt, 1u) == NCTA - 1u) {
            atomicExch(&g_cnt, 0u);
            __threadfence();
            atomicAdd(&g_gen, 1u);
        } else {
            while (*(volatile unsigned*)&g_gen == my) __nanosleep(32);
        }
        __threadfence();
    }
    __syncthreads();
}

// ---------------- m16n8k8 tf32 mma, fp32 accumulate ----------------
__device__ __forceinline__ void mma8(float* d, float a0, float a1, float a2, float a3,
                                     float b0, float b1) {
    asm volatile(
        "mma.sync.aligned.m16n8k8.row.col.f32.tf32.tf32.f32 "
        "{%0,%1,%2,%3}, {%4,%5,%6,%7}, {%8,%9}, {%0,%1,%2,%3};"
        : "+f"(d[0]), "+f"(d[1]), "+f"(d[2]), "+f"(d[3])
        : "r"(__float_as_uint(a0)), "r"(__float_as_uint(a1)),
          "r"(__float_as_uint(a2)), "r"(__float_as_uint(a3)),
          "r"(__float_as_uint(b0)), "r"(__float_as_uint(b1)));
}

__global__ __launch_bounds__(NTHR, 2)
void k_fused(const float* __restrict__ cemb, const float* __restrict__ memb,
             const float* __restrict__ Wc,   const float* __restrict__ bc,
             const float* __restrict__ Wg,   const float* __restrict__ att,
             const float* __restrict__ bg,   const float* __restrict__ he,
             float* __restrict__ out) {
    // union'd shared memory: sAm | sBn/sKB+sKA | softmax scratch
    __shared__ __align__(16) float smem[1152 + 4352 + 1280 + 160];
    float (*sAm)[P_AM] = (float(*)[P_AM])smem;                       // 32 x 36 = 1152
    float (*sBn)[P_BN] = (float(*)[P_BN])(smem + 1152);              // 128 x 36 = 4608 (aliases sKB+sKA)
    float (*sKB)[P_KB] = (float(*)[P_KB])(smem + 1152);              // 32 x 136 = 4352
    float (*sKA)[P_KA] = (float(*)[P_KA])(smem + 1152 + 4352);       // 32 x 40 = 1280
    float* sX   = smem + 1152 + 4352 + 1280;                         // 128
    float* s_an = sX + 128;                                          // 16

    const int cta = blockIdx.x;
    const int t   = threadIdx.x;
    const int w   = t >> 5, lane = t & 31;
    const int g   = lane >> 2, c = lane & 3;
    const int m0w = (w & 1) * 16;     // gemm2/3 warp m-offset (CTA tile 32)
    const int n0w = (w >> 1) * 32;    // gemm2/3 warp n-offset
    const int gid = cta * NTHR + t;
    const int tot = NCTA * NTHR;

    // ======== Phase 1: gemm1 (160 CTAs, full-K, atomic-free) + colsums + vb ========
    if (cta < 160) {
        // x_lin[m0..m0+16) = comb @ Wg^T; CTA tile 16x128, K=256 (8 subchunks), double-buffered
        int m0 = cta * 16;
        const float* Ab = (m0 < ND) ? cemb + (size_t)m0 * IN_ : memb + (size_t)(m0 - ND) * IN_;
        if (t < OC) sX[t] = att[t];
        if (t < 16) s_an[t] = 0.f;
        const int nw = w * 16;                 // warp tile m16 x n16
        const int am = t >> 3, ao4 = (t & 7) * 4;       // A-tile coords (t<128)
        float acc[2][4] = {};
        float4 ra, rb[4];
        // prologue: load subchunk 0
        if (t < 128) ra = *(const float4*)(Ab + (size_t)am * IN_ + ao4);
#pragma unroll
        for (int i = 0; i < 4; i++) {
            int n = i * 32 + (t >> 3);
            rb[i] = *(const float4*)(Wg + (size_t)n * IN_ + ao4);
        }
        for (int sub = 0; sub < 8; sub++) {
            if (t < 128) *(float4*)&sAm[am][ao4] = tf4(ra);
#pragma unroll
            for (int i = 0; i < 4; i++) *(float4*)&sBn[i * 32 + (t >> 3)][ao4] = tf4(rb[i]);
            __syncthreads();
            if (sub < 7) {                      // prefetch next subchunk (overlaps MMA)
                int k0n = (sub + 1) * 32;
                if (t < 128) ra = *(const float4*)(Ab + (size_t)am * IN_ + k0n + ao4);
#pragma unroll
                for (int i = 0; i < 4; i++) {
                    int n = i * 32 + (t >> 3);
                    rb[i] = *(const float4*)(Wg + (size_t)n * IN_ + k0n + ao4);
                }
            }
#pragma unroll
            for (int ks = 0; ks < 4; ks++) {
                int kc = ks * 8 + c;
                float a0 = sAm[g][kc],     a0h = sAm[g][kc + 4];
                float a1 = sAm[g + 8][kc], a1h = sAm[g + 8][kc + 4];
#pragma unroll
                for (int ni = 0; ni < 2; ni++) {
                    float bx = sBn[nw + ni * 8 + g][kc];
                    float by = sBn[nw + ni * 8 + g][kc + 4];
                    mma8(acc[ni], a0, a1, a0h, a1h, bx, by);
                }
            }
            __syncthreads();
        }
        // direct store x_lin + fused a_node (smem reduce, direct store)
        float an0 = 0.f, an8 = 0.f;
#pragma unroll
        for (int ni = 0; ni < 2; ni++) {
            int col = nw + ni * 8 + 2 * c;
            *(float2*)&g_xlin[(size_t)(m0 + g) * OC + col]     = make_float2(acc[ni][0], acc[ni][1]);
            *(float2*)&g_xlin[(size_t)(m0 + g + 8) * OC + col] = make_float2(acc[ni][2], acc[ni][3]);
            an0 += acc[ni][0] * sX[col] + acc[ni][1] * sX[col + 1];
            an8 += acc[ni][2] * sX[col] + acc[ni][3] * sX[col + 1];
        }
        an0 += __shfl_xor_sync(0xffffffffu, an0, 1);
        an0 += __shfl_xor_sync(0xffffffffu, an0, 2);
        an8 += __shfl_xor_sync(0xffffffffu, an8, 1);
        an8 += __shfl_xor_sync(0xffffffffu, an8, 2);
        if (c == 0) { atomicAdd(&s_an[g], an0); atomicAdd(&s_an[g + 8], an8); }
        __syncthreads();
        if (t < 16) g_anode[m0 + t] = s_an[t];
    } else if (cta < 240) {
        int b = cta - 160;
        const float* base = (b < 64) ? (cemb + (size_t)b * 32 * IN_)
                                     : (memb + (size_t)(b - 64) * 32 * IN_);
        float s = 0.f;
#pragma unroll
        for (int r = 0; r < 32; r++) s += base[r * IN_ + t];
        atomicAdd((b < 64) ? &g_meanc[t] : &g_meanm[t], s);
    } else if (cta == 240) {
        float s = 0.f;
        for (int o = 0; o < OC; o++) s += Wg[o * IN_ + t] * att[OC + o];
        g_vb[t] = s;
    }
    gsync();

    // ======== Phase 2: softmax (2048 warp-rows) + conv vectors ========
    {
        float* sf = smem;          // sanm[512] + svb[256]
        if (cta < 256) {
            sf[t]       = g_anode[ND + t];
            sf[256 + t] = g_anode[ND + 256 + t];
            sf[512 + t] = g_vb[t];
        }
        __syncthreads();
        if (cta < 256) {
            int d = cta * 8 + w;
            const float* hb = he + (size_t)d * IN_;
            float ah = 0.f;
#pragma unroll
            for (int j = 0; j < 8; j++) { int i = lane + j * 32; ah += hb[i] * sf[512 + i]; }
#pragma unroll
            for (int s = 16; s > 0; s >>= 1) ah += __shfl_xor_sync(0xffffffffu, ah, s);
            float l[16];
            float mx = -1e30f;
#pragma unroll
            for (int j = 0; j < 16; j++) { l[j] = lrelu(sf[lane + j * 32] + ah); mx = fmaxf(mx, l[j]); }
            float l0 = lrelu(g_anode[d] + ah);
            mx = fmaxf(mx, l0);
#pragma unroll
            for (int s = 16; s > 0; s >>= 1) mx = fmaxf(mx, __shfl_xor_sync(0xffffffffu, mx, s));
            float psum = 0.f;
#pragma unroll
            for (int j = 0; j < 16; j++) { l[j] = __expf(l[j] - mx); psum += l[j]; }
#pragma unroll
            for (int s = 16; s > 0; s >>= 1) psum += __shfl_xor_sync(0xffffffffu, psum, s);
            float e0 = __expf(l0 - mx);
            float inv = 1.f / (psum + e0);
#pragma unroll
            for (int j = 0; j < 16; j++) g_E[(size_t)d * NM + lane + j * 32] = l[j] * inv;
            if (lane == 0) g_alpha0[d] = e0 * inv;
        } else if (cta < 288) {
            int gi = (cta - 256) * 8 + w;   // 0-127 convc, 128-255 convm
            int o = gi & 127;
            const float* mean = (gi < 128) ? g_meanc : g_meanm;
            float s = 0.f;
#pragma unroll
            for (int j = 0; j < 8; j++) { int i = lane + j * 32; s += Wc[o * IN_ + i] * mean[i]; }
#pragma unroll
            for (int sh = 16; sh > 0; sh >>= 1) s += __shfl_xor_sync(0xffffffffu, s, sh);
            if (lane == 0) {
                if (gi < 128) g_convc[o] = s * (1.f / ND) + bc[o];
                else          g_convm[o] = s * (1.f / NM) + bc[o];
            }
        }
    }
    gsync();

    // ======== Phase 3: gemm2 partials p2[s] = E[:,ks] @ xlin_med[ks,:] (256 CTAs) ========
    if (cta < 256) {
        int m0 = (cta >> 2) * 32;          // 64 m-tiles of 32
        int ksp = cta & 3;                 // ksplit 4, chunk 128
        int kb = ksp * 128;
        const int am = t >> 3, ao4 = (t & 7) * 4;    // A coords: 32 x 32
        const int bk = w, bn4 = lane * 4;            // B coords: k = i*8+w, n = lane*4
        const float* Bb = g_xlin + (size_t)ND * OC;
        float acc[4][4] = {};
        float4 ra, rb[4];
        ra = *(const float4*)(&g_E[(size_t)(m0 + am) * NM + kb + ao4]);
#pragma unroll
        for (int i = 0; i < 4; i++)
            rb[i] = *(const float4*)(Bb + (size_t)(kb + i * 8 + bk) * OC + bn4);
        for (int sub = 0; sub < 4; sub++) {
            *(float4*)&sAm[am][ao4] = tf4(ra);
#pragma unroll
            for (int i = 0; i < 4; i++) *(float4*)&sKB[i * 8 + bk][bn4] = tf4(rb[i]);
            __syncthreads();
            if (sub < 3) {
                int k0n = kb + (sub + 1) * 32;
                ra = *(const float4*)(&g_E[(size_t)(m0 + am) * NM + k0n + ao4]);
#pragma unroll
                for (int i = 0; i < 4; i++)
                    rb[i] = *(const float4*)(Bb + (size_t)(k0n + i * 8 + bk) * OC + bn4);
            }
#pragma unroll
            for (int ks = 0; ks < 4; ks++) {
                int kc = ks * 8 + c;
                float a0 = sAm[m0w + g][kc],     a0h = sAm[m0w + g][kc + 4];
                float a1 = sAm[m0w + g + 8][kc], a1h = sAm[m0w + g + 8][kc + 4];
#pragma unroll
                for (int ni = 0; ni < 4; ni++) {
                    float bx = sKB[kc][n0w + ni * 8 + g];
                    float by = sKB[kc + 4][n0w + ni * 8 + g];
                    mma8(acc[ni], a0, a1, a0h, a1h, bx, by);
                }
            }
            __syncthreads();
        }
        float* dst = g_p2 + (size_t)ksp * NDOC;
        int r0 = m0 + m0w + g;
#pragma unroll
        for (int ni = 0; ni < 4; ni++) {
            int col = n0w + ni * 8 + 2 * c;
            *(float2*)&dst[(size_t)r0 * OC + col]       = make_float2(acc[ni][0], acc[ni][1]);
            *(float2*)&dst[(size_t)(r0 + 8) * OC + col] = make_float2(acc[ni][2], acc[ni][3]);
        }
    }
    gsync();

    // ======== Phase 4: epilogue 1 (sum partials -> e, disease rows) + mean resets ========
    for (int idx = gid; idx < NDOC; idx += tot) {
        int d = idx >> 7, n = idx & 127;
        float p = g_p2[idx] + g_p2[NDOC + idx] + g_p2[2 * NDOC + idx] + g_p2[3 * NDOC + idx];
        float a0 = g_alpha0[d];
        float e  = (a0 * g_xlin[idx] + p) * (1.f / NEDG);
        g_e[idx] = e;
        out[(size_t)d * (2 * OC) + n]      = a0 * e + bg[n];
        out[(size_t)d * (2 * OC) + OC + n] = g_convc[n];
    }
    if (gid < IN_) g_meanc[gid] = 0.f;
    else if (gid < 2 * IN_) g_meanm[gid - IN_] = 0.f;
    gsync();

    // ======== Phase 5: gemm3 partials p3[s] = E^T[:,ks] @ e[ks,:] (256 CTAs) ========
    if (cta < 256) {
        int m0 = (cta >> 4) * 32;          // 16 m-tiles of 32
        int ksp = cta & 15;                // ksplit 16, chunk 128
        int kb = ksp * 128;
        const int ak = t >> 3, am4 = (t & 7) * 4;    // A (E^T): k = t>>3, m4 contiguous
        const int bk = w, bn4 = lane * 4;
        float acc[4][4] = {};
        float4 ra, rb[4];
        ra = *(const float4*)(&g_E[(size_t)(kb + ak) * NM + m0 + am4]);
#pragma unroll
        for (int i = 0; i < 4; i++)
            rb[i] = *(const float4*)(g_e + (size_t)(kb + i * 8 + bk) * OC + bn4);
        for (int sub = 0; sub < 4; sub++) {
            *(float4*)&sKA[ak][am4] = tf4(ra);
#pragma unroll
            for (int i = 0; i < 4; i++) *(float4*)&sKB[i * 8 + bk][bn4] = tf4(rb[i]);
            __syncthreads();
            if (sub < 3) {
                int k0n = kb + (sub + 1) * 32;
                ra = *(const float4*)(&g_E[(size_t)(k0n + ak) * NM + m0 + am4]);
#pragma unroll
                for (int i = 0; i < 4; i++)
                    rb[i] = *(const float4*)(g_e + (size_t)(k0n + i * 8 + bk) * OC + bn4);
            }
#pragma unroll
            for (int ks = 0; ks < 4; ks++) {
                int kc = ks * 8 + c;
                float a0 = sKA[kc][m0w + g],     a0h = sKA[kc + 4][m0w + g];
                float a1 = sKA[kc][m0w + g + 8], a1h = sKA[kc + 4][m0w + g + 8];
#pragma unroll
                for (int ni = 0; ni < 4; ni++) {
                    float bx = sKB[kc][n0w + ni * 8 + g];
                    float by = sKB[kc + 4][n0w + ni * 8 + g];
                    mma8(acc[ni], a0, a1, a0h, a1h, bx, by);
                }
            }
            __syncthreads();
        }
        float* dst = g_p3 + (size_t)ksp * NMOC;
        int r0 = m0 + m0w + g;
#pragma unroll
        for (int ni = 0; ni < 4; ni++) {
            int col = n0w + ni * 8 + 2 * c;
            *(float2*)&dst[(size_t)r0 * OC + col]       = make_float2(acc[ni][0], acc[ni][1]);
            *(float2*)&dst[(size_t)(r0 + 8) * OC + col] = make_float2(acc[ni][2], acc[ni][3]);
        }
    }
    gsync();

    // ======== Phase 6: epilogue 2 (sum 16 partials -> medicine rows) ========
    for (int idx = gid; idx < NMOC; idx += tot) {
        int m = idx >> 7, n = idx & 127;
        float s = 0.f;
#pragma unroll
        for (int si = 0; si < 16; si++) s += g_p3[(size_t)si * NMOC + idx];
        out[(size_t)(ND + m) * (2 * OC) + n]      = s * (1.f / ND) + bg[n];
        out[(size_t)(ND + m) * (2 * OC) + OC + n] = g_convm[n];
    }
}

// ---------------- launch: ONE kernel ----------------
extern "C" void kernel_launch(void* const* d_in, const int* in_sizes, int n_in,
                              void* d_out, int out_size) {
    const float* cemb = (const float*)d_in[2];
    const float* memb = (const float*)d_in[3];
    const float* Wc   = (const float*)d_in[4];
    const float* bc   = (const float*)d_in[5];
    const float* Wg   = (const float*)d_in[6];
    const float* att  = (const float*)d_in[7];
    const float* bg   = (const float*)d_in[8];
    const float* he   = (const float*)d_in[9];
    float* out = (float*)d_out;

    k_fused<<<NCTA, NTHR>>>(cemb, memb, Wc, bc, Wg, att, bg, he, out);
}

// round 15
// speedup vs baseline: 3.0156x; 1.0734x over previous
#include <cuda_runtime.h>

// Problem dims (fixed)
#define ND   2048
#define NM   512
#define IN_  256
#define OC   128
#define NTOT 2560
#define NEDG 513
#define NCTA 296
#define NTHR 256
#define NDOC (ND * OC)
#define NMOC (NM * OC)

// ---------------- device scratch ----------------
__device__ float g_xlin[NTOT * OC];
__device__ float g_anode[NTOT];
__device__ float g_E[ND * NM];
__device__ float g_alpha0[ND];
__device__ float g_e[NDOC];
__device__ float g_p2[4 * NDOC];        // gemm2 split-K partials
__device__ float g_p3[16 * NMOC];       // gemm3 split-K partials
__device__ float g_meanc[IN_], g_meanm[IN_], g_vb[IN_];
__device__ float g_convc[OC], g_convm[OC];
__device__ unsigned g_gen, g_cnt;

__device__ __forceinline__ float lrelu(float x) { return x > 0.f ? x : 0.2f * x; }

// ---------------- cp.async helpers ----------------
__device__ __forceinline__ void cpa16(float* dst_smem, const float* src) {
    unsigned d = (unsigned)__cvta_generic_to_shared(dst_smem);
    asm volatile("cp.async.cg.shared.global [%0], [%1], 16;" :: "r"(d), "l"(src));
}
#define CP_COMMIT() asm volatile("cp.async.commit_group;" ::: "memory")
#define CP_WAIT0()  asm volatile("cp.async.wait_group 0;" ::: "memory")

// ---------------- sense-reversing software grid barrier ----------------
__device__ __forceinline__ void gsync() {
    __syncthreads();
    if (threadIdx.x == 0) {
        __threadfence();
        unsigned my = *(volatile unsigned*)&g_gen;
        if (atomicAdd(&g_cnt, 1u) == NCTA - 1u) {
            atomicExch(&g_cnt, 0u);
            __threadfence();
            atomicAdd(&g_gen, 1u);
        } else {
            while (*(volatile unsigned*)&g_gen == my) __nanosleep(32);
        }
        __threadfence();
    }
    __syncthreads();
}

// ---------------- m16n8k8 tf32 mma, fp32 accumulate ----------------
__device__ __forceinline__ void mma8(float* d, float a0, float a1, float a2, float a3,
                                     float b0, float b1) {
    asm volatile(
        "mma.sync.aligned.m16n8k8.row.col.f32.tf32.tf32.f32 "
        "{%0,%1,%2,%3}, {%4,%5,%6,%7}, {%8,%9}, {%0,%1,%2,%3};"
        : "+f"(d[0]), "+f"(d[1]), "+f"(d[2]), "+f"(d[3])
        : "r"(__float_as_uint(a0)), "r"(__float_as_uint(a1)),
          "r"(__float_as_uint(a2)), "r"(__float_as_uint(a3)),
          "r"(__float_as_uint(b0)), "r"(__float_as_uint(b1)));
}

// smem pool (floats). Phase layouts (double-buffered):
//  P1: A bufs @0,576 (16x36); B bufs @1152,5760 (128x36)           end 10368
//  P3: A bufs @0,1152 (32x36); B bufs @2304,6656 (32x136)          end 11008
//  P5: A bufs @0,1280 (32x40 k-major); B bufs @2560,6912 (32x136)  end 11264
//  sX @11264 (128), s_an @11392 (16); softmax scratch @0 (768)
#define SMEMF 11424

__global__ __launch_bounds__(NTHR, 2)
void k_fused(const float* __restrict__ cemb, const float* __restrict__ memb,
             const float* __restrict__ Wc,   const float* __restrict__ bc,
             const float* __restrict__ Wg,   const float* __restrict__ att,
             const float* __restrict__ bg,   const float* __restrict__ he,
             float* __restrict__ out) {
    __shared__ __align__(16) float smem[SMEMF];
    float* sX   = smem + 11264;
    float* s_an = smem + 11392;

    const int cta = blockIdx.x;
    const int t   = threadIdx.x;
    const int w   = t >> 5, lane = t & 31;
    const int g   = lane >> 2, c = lane & 3;
    const int m0w = (w & 1) * 16;     // gemm2/3 warp m-offset (CTA tile 32)
    const int n0w = (w >> 1) * 32;    // gemm2/3 warp n-offset
    const int gid = cta * NTHR + t;
    const int tot = NCTA * NTHR;

    // ======== Phase 1: gemm1 (160 CTAs, full-K) + colsums + vb ========
    if (cta < 160) {
        // x_lin[m0..m0+16) = comb @ Wg^T; CTA tile 16x128, K=256 = 8 subchunks, cp.async pipeline
        int m0 = cta * 16;
        const float* Ab = (m0 < ND) ? cemb + (size_t)m0 * IN_ : memb + (size_t)(m0 - ND) * IN_;
        if (t < OC) sX[t] = att[t];
        if (t < 16) s_an[t] = 0.f;
        const int nw = w * 16;                        // warp tile m16 x n16
        const int am = t >> 3, ao4 = (t & 7) * 4;     // tile coords
        float acc[2][4] = {};
        // prologue: subchunk 0 -> buf 0
        if (t < 128) cpa16(smem + am * 36 + ao4, Ab + (size_t)am * IN_ + ao4);
#pragma unroll
        for (int i = 0; i < 4; i++) {
            int n = i * 32 + am;
            cpa16(smem + 1152 + n * 36 + ao4, Wg + (size_t)n * IN_ + ao4);
        }
        CP_COMMIT();
        for (int sub = 0; sub < 8; sub++) {
            int buf = sub & 1;
            CP_WAIT0();
            __syncthreads();
            if (sub < 7) {                            // issue next subchunk (overlaps MMA)
                int k0n = (sub + 1) * 32, nb = buf ^ 1;
                if (t < 128) cpa16(smem + nb * 576 + am * 36 + ao4,
                                   Ab + (size_t)am * IN_ + k0n + ao4);
#pragma unroll
                for (int i = 0; i < 4; i++) {
                    int n = i * 32 + am;
                    cpa16(smem + 1152 + nb * 4608 + n * 36 + ao4,
                          Wg + (size_t)n * IN_ + k0n + ao4);
                }
                CP_COMMIT();
            }
            const float* A_ = smem + buf * 576;
            const float* B_ = smem + 1152 + buf * 4608;
#pragma unroll
            for (int ks = 0; ks < 4; ks++) {
                int kc = ks * 8 + c;
                float a0 = A_[g * 36 + kc],       a0h = A_[g * 36 + kc + 4];
                float a1 = A_[(g + 8) * 36 + kc], a1h = A_[(g + 8) * 36 + kc + 4];
#pragma unroll
                for (int ni = 0; ni < 2; ni++) {
                    float bx = B_[(nw + ni * 8 + g) * 36 + kc];
                    float by = B_[(nw + ni * 8 + g) * 36 + kc + 4];
                    mma8(acc[ni], a0, a1, a0h, a1h, bx, by);
                }
            }
        }
        // direct store x_lin + fused a_node (smem reduce, direct store)
        float an0 = 0.f, an8 = 0.f;
#pragma unroll
        for (int ni = 0; ni < 2; ni++) {
            int col = nw + ni * 8 + 2 * c;
            *(float2*)&g_xlin[(size_t)(m0 + g) * OC + col]     = make_float2(acc[ni][0], acc[ni][1]);
            *(float2*)&g_xlin[(size_t)(m0 + g + 8) * OC + col] = make_float2(acc[ni][2], acc[ni][3]);
            an0 += acc[ni][0] * sX[col] + acc[ni][1] * sX[col + 1];
            an8 += acc[ni][2] * sX[col] + acc[ni][3] * sX[col + 1];
        }
        an0 += __shfl_xor_sync(0xffffffffu, an0, 1);
        an0 += __shfl_xor_sync(0xffffffffu, an0, 2);
        an8 += __shfl_xor_sync(0xffffffffu, an8, 1);
        an8 += __shfl_xor_sync(0xffffffffu, an8, 2);
        if (c == 0) { atomicAdd(&s_an[g], an0); atomicAdd(&s_an[g + 8], an8); }
        __syncthreads();
        if (t < 16) g_anode[m0 + t] = s_an[t];
    } else if (cta < 240) {
        int b = cta - 160;
        const float* base = (b < 64) ? (cemb + (size_t)b * 32 * IN_)
                                     : (memb + (size_t)(b - 64) * 32 * IN_);
        float s = 0.f;
#pragma unroll
        for (int r = 0; r < 32; r++) s += base[r * IN_ + t];
        atomicAdd((b < 64) ? &g_meanc[t] : &g_meanm[t], s);
    } else if (cta == 240) {
        float s = 0.f;
        for (int o = 0; o < OC; o++) s += Wg[o * IN_ + t] * att[OC + o];
        g_vb[t] = s;
    }
    gsync();

    // ======== Phase 2: softmax (2048 warp-rows) + conv vectors ========
    {
        float* sf = smem;          // sanm[512] + svb[256]
        if (cta < 256) {
            sf[t]       = g_anode[ND + t];
            sf[256 + t] = g_anode[ND + 256 + t];
            sf[512 + t] = g_vb[t];
        }
        __syncthreads();
        if (cta < 256) {
            int d = cta * 8 + w;
            const float* hb = he + (size_t)d * IN_;
            float ah = 0.f;
#pragma unroll
            for (int j = 0; j < 8; j++) { int i = lane + j * 32; ah += hb[i] * sf[512 + i]; }
#pragma unroll
            for (int s = 16; s > 0; s >>= 1) ah += __shfl_xor_sync(0xffffffffu, ah, s);
            float l[16];
            float mx = -1e30f;
#pragma unroll
            for (int j = 0; j < 16; j++) { l[j] = lrelu(sf[lane + j * 32] + ah); mx = fmaxf(mx, l[j]); }
            float l0 = lrelu(g_anode[d] + ah);
            mx = fmaxf(mx, l0);
#pragma unroll
            for (int s = 16; s > 0; s >>= 1) mx = fmaxf(mx, __shfl_xor_sync(0xffffffffu, mx, s));
            float psum = 0.f;
#pragma unroll
            for (int j = 0; j < 16; j++) { l[j] = __expf(l[j] - mx); psum += l[j]; }
#pragma unroll
            for (int s = 16; s > 0; s >>= 1) psum += __shfl_xor_sync(0xffffffffu, psum, s);
            float e0 = __expf(l0 - mx);
            float inv = 1.f / (psum + e0);
#pragma unroll
            for (int j = 0; j < 16; j++) g_E[(size_t)d * NM + lane + j * 32] = l[j] * inv;
            if (lane == 0) g_alpha0[d] = e0 * inv;
        } else if (cta < 288) {
            int gi = (cta - 256) * 8 + w;   // 0-127 convc, 128-255 convm
            int o = gi & 127;
            const float* mean = (gi < 128) ? g_meanc : g_meanm;
            float s = 0.f;
#pragma unroll
            for (int j = 0; j < 8; j++) { int i = lane + j * 32; s += Wc[o * IN_ + i] * mean[i]; }
#pragma unroll
            for (int sh = 16; sh > 0; sh >>= 1) s += __shfl_xor_sync(0xffffffffu, s, sh);
            if (lane == 0) {
                if (gi < 128) g_convc[o] = s * (1.f / ND) + bc[o];
                else          g_convm[o] = s * (1.f / NM) + bc[o];
            }
        }
    }
    gsync();

    // ======== Phase 3: gemm2 partials p2[s] = E[:,ks] @ xlin_med[ks,:] (256 CTAs) ========
    if (cta < 256) {
        int m0 = (cta >> 2) * 32;          // 64 m-tiles of 32
        int ksp = cta & 3;                 // ksplit 4, chunk 128 = 4 subchunks
        int kb = ksp * 128;
        const int am = t >> 3, ao4 = (t & 7) * 4;    // A coords: 32 x 32
        const int bk = w, bn4 = lane * 4;            // B coords: k = i*8+w, n4
        const float* Bb = g_xlin + (size_t)ND * OC;
        float acc[4][4] = {};
        // prologue
        cpa16(smem + am * 36 + ao4, g_E + (size_t)(m0 + am) * NM + kb + ao4);
#pragma unroll
        for (int i = 0; i < 4; i++)
            cpa16(smem + 2304 + (i * 8 + bk) * 136 + bn4,
                  Bb + (size_t)(kb + i * 8 + bk) * OC + bn4);
        CP_COMMIT();
        for (int sub = 0; sub < 4; sub++) {
            int buf = sub & 1;
            CP_WAIT0();
            __syncthreads();
            if (sub < 3) {
                int k0n = kb + (sub + 1) * 32, nb = buf ^ 1;
                cpa16(smem + nb * 1152 + am * 36 + ao4,
                      g_E + (size_t)(m0 + am) * NM + k0n + ao4);
#pragma unroll
                for (int i = 0; i < 4; i++)
                    cpa16(smem + 2304 + nb * 4352 + (i * 8 + bk) * 136 + bn4,
                          Bb + (size_t)(k0n + i * 8 + bk) * OC + bn4);
                CP_COMMIT();
            }
            const float* A_ = smem + buf * 1152;
            const float* B_ = smem + 2304 + buf * 4352;
#pragma unroll
            for (int ks = 0; ks < 4; ks++) {
                int kc = ks * 8 + c;
                float a0 = A_[(m0w + g) * 36 + kc],     a0h = A_[(m0w + g) * 36 + kc + 4];
                float a1 = A_[(m0w + g + 8) * 36 + kc], a1h = A_[(m0w + g + 8) * 36 + kc + 4];
#pragma unroll
                for (int ni = 0; ni < 4; ni++) {
                    float bx = B_[kc * 136 + n0w + ni * 8 + g];
                    float by = B_[(kc + 4) * 136 + n0w + ni * 8 + g];
                    mma8(acc[ni], a0, a1, a0h, a1h, bx, by);
                }
            }
        }
        float* dst = g_p2 + (size_t)ksp * NDOC;
        int r0 = m0 + m0w + g;
#pragma unroll
        for (int ni = 0; ni < 4; ni++) {
            int col = n0w + ni * 8 + 2 * c;
            *(float2*)&dst[(size_t)r0 * OC + col]       = make_float2(acc[ni][0], acc[ni][1]);
            *(float2*)&dst[(size_t)(r0 + 8) * OC + col] = make_float2(acc[ni][2], acc[ni][3]);
        }
    }
    gsync();

    // ======== Phase 4: epilogue 1 (sum partials -> e, disease rows) + mean resets ========
    for (int idx = gid; idx < NDOC; idx += tot) {
        int d = idx >> 7, n = idx & 127;
        float p = g_p2[idx] + g_p2[NDOC + idx] + g_p2[2 * NDOC + idx] + g_p2[3 * NDOC + idx];
        float a0 = g_alpha0[d];
        float e  = (a0 * g_xlin[idx] + p) * (1.f / NEDG);
        g_e[idx] = e;
        out[(size_t)d * (2 * OC) + n]      = a0 * e + bg[n];
        out[(size_t)d * (2 * OC) + OC + n] = g_convc[n];
    }
    if (gid < IN_) g_meanc[gid] = 0.f;
    else if (gid < 2 * IN_) g_meanm[gid - IN_] = 0.f;
    gsync();

    // ======== Phase 5: gemm3 partials p3[s] = E^T[:,ks] @ e[ks,:] (256 CTAs) ========
    if (cta < 256) {
        int m0 = (cta >> 4) * 32;          // 16 m-tiles of 32
        int ksp = cta & 15;                // ksplit 16, chunk 128 = 4 subchunks
        int kb = ksp * 128;
        const int ak = t >> 3, am4 = (t & 7) * 4;    // A (E^T) coords: 32 k x 32 m
        const int bk = w, bn4 = lane * 4;
        float acc[4][4] = {};
        // prologue
        cpa16(smem + ak * 40 + am4, g_E + (size_t)(kb + ak) * NM + m0 + am4);
#pragma unroll
        for (int i = 0; i < 4; i++)
            cpa16(smem + 2560 + (i * 8 + bk) * 136 + bn4,
                  g_e + (size_t)(kb + i * 8 + bk) * OC + bn4);
        CP_COMMIT();
        for (int sub = 0; sub < 4; sub++) {
            int buf = sub & 1;
            CP_WAIT0();
            __syncthreads();
            if (sub < 3) {
                int k0n = kb + (sub + 1) * 32, nb = buf ^ 1;
                cpa16(smem + nb * 1280 + ak * 40 + am4,
                      g_E + (size_t)(k0n + ak) * NM + m0 + am4);
#pragma unroll
                for (int i = 0; i < 4; i++)
                    cpa16(smem + 2560 + nb * 4352 + (i * 8 + bk) * 136 + bn4,
                          g_e + (size_t)(k0n + i * 8 + bk) * OC + bn4);
                CP_COMMIT();
            }
            const float* A_ = smem + buf * 1280;
            const float* B_ = smem + 2560 + buf * 4352;
#pragma unroll
            for (int ks = 0; ks < 4; ks++) {
                int kc = ks * 8 + c;
                float a0 = A_[kc * 40 + m0w + g],       a0h = A_[(kc + 4) * 40 + m0w + g];
                float a1 = A_[kc * 40 + m0w + g + 8],   a1h = A_[(kc + 4) * 40 + m0w + g + 8];
#pragma unroll
                for (int ni = 0; ni < 4; ni++) {
                    float bx = B_[kc * 136 + n0w + ni * 8 + g];
                    float by = B_[(kc + 4) * 136 + n0w + ni * 8 + g];
                    mma8(acc[ni], a0, a1, a0h, a1h, bx, by);
                }
            }
        }
        float* dst = g_p3 + (size_t)ksp * NMOC;
        int r0 = m0 + m0w + g;
#pragma unroll
        for (int ni = 0; ni < 4; ni++) {
            int col = n0w + ni * 8 + 2 * c;
            *(float2*)&dst[(size_t)r0 * OC + col]       = make_float2(acc[ni][0], acc[ni][1]);
            *(float2*)&dst[(size_t)(r0 + 8) * OC + col] = make_float2(acc[ni][2], acc[ni][3]);
        }
    }
    gsync();

    // ======== Phase 6: epilogue 2 (sum 16 partials -> medicine rows) ========
    for (int idx = gid; idx < NMOC; idx += tot) {
        int m = idx >> 7, n = idx & 127;
        float s = 0.f;
#pragma unroll
        for (int si = 0; si < 16; si++) s += g_p3[(size_t)si * NMOC + idx];
        out[(size_t)(ND + m) * (2 * OC) + n]      = s * (1.f / ND) + bg[n];
        out[(size_t)(ND + m) * (2 * OC) + OC + n] = g_convm[n];
    }
}

// ---------------- launch: ONE kernel ----------------
extern "C" void kernel_launch(void* const* d_in, const int* in_sizes, int n_in,
                              void* d_out, int out_size) {
    const float* cemb = (const float*)d_in[2];
    const float* memb = (const float*)d_in[3];
    const float* Wc   = (const float*)d_in[4];
    const float* bc   = (const float*)d_in[5];
    const float* Wg   = (const float*)d_in[6];
    const float* att  = (const float*)d_in[7];
    const float* bg   = (const float*)d_in[8];
    const float* he   = (const float*)d_in[9];
    float* out = (float*)d_out;

    k_fused<<<NCTA, NTHR>>>(cemb, memb, Wc, bc, Wg, att, bg, he, out);
}

// round 16
// speedup vs baseline: 3.1068x; 1.0302x over previous
#include <cuda_runtime.h>

// Problem dims (fixed)
#define ND   2048
#define NM   512
#define IN_  256
#define OC   128
#define NTOT 2560
#define NEDG 513
#define NCTA 296
#define NTHR 256
#define NDOC (ND * OC)
#define NMOC (NM * OC)

// smem stage sizes/offsets (floats); 3-stage pipelines, regions overlap per phase
#define A1S 576      // P1 A stage: 16 x 36
#define B1S 4608     // P1 B stage: 128 x 36
#define B1O 1728     // P1 B base (3 x A1S)
#define A3S 1152     // P3 A stage: 32 x 36
#define B3S 4352     // P3/P5 B stage: 32 x 136
#define B3O 3456     // P3 B base
#define A5S 1280     // P5 A stage: 32 x 40 (k-major)
#define B5O 3840     // P5 B base
#define SX_OFF  16896
#define SAN_OFF 17024
#define SMEMF   17040                    // floats
#define SMEMB   (SMEMF * 4)              // bytes = 68160

// ---------------- device scratch ----------------
__device__ float g_xlin[NTOT * OC];
__device__ float g_anode[NTOT];
__device__ float g_E[ND * NM];
__device__ float g_alpha0[ND];
__device__ float g_e[NDOC];
__device__ float g_p2[4 * NDOC];        // gemm2 split-K partials
__device__ float g_p3[16 * NMOC];       // gemm3 split-K partials
__device__ float g_meanc[IN_], g_meanm[IN_], g_vb[IN_];
__device__ float g_convc[OC], g_convm[OC];
__device__ unsigned g_gen, g_cnt;

__device__ __forceinline__ float lrelu(float x) { return x > 0.f ? x : 0.2f * x; }

// ---------------- cp.async helpers ----------------
__device__ __forceinline__ void cpa16(float* dst_smem, const float* src) {
    unsigned d = (unsigned)__cvta_generic_to_shared(dst_smem);
    asm volatile("cp.async.cg.shared.global [%0], [%1], 16;" :: "r"(d), "l"(src));
}
#define CP_COMMIT() asm volatile("cp.async.commit_group;" ::: "memory")
#define CP_WAIT0()  asm volatile("cp.async.wait_group 0;" ::: "memory")
#define CP_WAIT1()  asm volatile("cp.async.wait_group 1;" ::: "memory")

// ---------------- sense-reversing software grid barrier ----------------
__device__ __forceinline__ void gsync() {
    __syncthreads();
    if (threadIdx.x == 0) {
        __threadfence();
        unsigned my = *(volatile unsigned*)&g_gen;
        if (atomicAdd(&g_cnt, 1u) == NCTA - 1u) {
            atomicExch(&g_cnt, 0u);
            __threadfence();
            atomicAdd(&g_gen, 1u);
        } else {
            while (*(volatile unsigned*)&g_gen == my) __nanosleep(32);
        }
        __threadfence();
    }
    __syncthreads();
}

// ---------------- m16n8k8 tf32 mma, fp32 accumulate ----------------
__device__ __forceinline__ void mma8(float* d, float a0, float a1, float a2, float a3,
                                     float b0, float b1) {
    asm volatile(
        "mma.sync.aligned.m16n8k8.row.col.f32.tf32.tf32.f32 "
        "{%0,%1,%2,%3}, {%4,%5,%6,%7}, {%8,%9}, {%0,%1,%2,%3};"
        : "+f"(d[0]), "+f"(d[1]), "+f"(d[2]), "+f"(d[3])
        : "r"(__float_as_uint(a0)), "r"(__float_as_uint(a1)),
          "r"(__float_as_uint(a2)), "r"(__float_as_uint(a3)),
          "r"(__float_as_uint(b0)), "r"(__float_as_uint(b1)));
}

__global__ __launch_bounds__(NTHR, 2)
void k_fused(const float* __restrict__ cemb, const float* __restrict__ memb,
             const float* __restrict__ Wc,   const float* __restrict__ bc,
             const float* __restrict__ Wg,   const float* __restrict__ att,
             const float* __restrict__ bg,   const float* __restrict__ he,
             float* __restrict__ out) {
    extern __shared__ __align__(16) float smem[];
    float* sX   = smem + SX_OFF;
    float* s_an = smem + SAN_OFF;

    const int cta = blockIdx.x;
    const int t   = threadIdx.x;
    const int w   = t >> 5, lane = t & 31;
    const int g   = lane >> 2, c = lane & 3;
    const int m0w = (w & 1) * 16;     // gemm2/3 warp m-offset (CTA tile 32)
    const int n0w = (w >> 1) * 32;    // gemm2/3 warp n-offset
    const int gid = cta * NTHR + t;
    const int tot = NCTA * NTHR;

    // ======== Phase 1: gemm1 (160 CTAs, full-K) + colsums + vb ========
    if (cta < 160) {
        // x_lin[m0..m0+16) = comb @ Wg^T; CTA 16x128, K=256 = 8 subchunks, 3-stage pipeline
        int m0 = cta * 16;
        const float* Ab = (m0 < ND) ? cemb + (size_t)m0 * IN_ : memb + (size_t)(m0 - ND) * IN_;
        if (t < OC) sX[t] = att[t];
        if (t < 16) s_an[t] = 0.f;
        const int nw = w * 16;                        // warp tile m16 x n16
        const int am = t >> 3, ao4 = (t & 7) * 4;     // tile coords
        float acc[2][4] = {};
        // prologue: issue subchunks 0,1
#pragma unroll
        for (int p = 0; p < 2; p++) {
            int k0 = p * 32;
            if (t < 128) cpa16(smem + p * A1S + am * 36 + ao4, Ab + (size_t)am * IN_ + k0 + ao4);
#pragma unroll
            for (int i = 0; i < 4; i++) {
                int n = i * 32 + am;
                cpa16(smem + B1O + p * B1S + n * 36 + ao4, Wg + (size_t)n * IN_ + k0 + ao4);
            }
            CP_COMMIT();
        }
        for (int sub = 0; sub < 8; sub++) {
            if (sub < 7) CP_WAIT1(); else CP_WAIT0();
            __syncthreads();
            if (sub < 6) {                            // issue sub+2 (2-ahead)
                int k0n = (sub + 2) * 32, nb = (sub + 2) % 3;
                if (t < 128) cpa16(smem + nb * A1S + am * 36 + ao4,
                                   Ab + (size_t)am * IN_ + k0n + ao4);
#pragma unroll
                for (int i = 0; i < 4; i++) {
                    int n = i * 32 + am;
                    cpa16(smem + B1O + nb * B1S + n * 36 + ao4,
                          Wg + (size_t)n * IN_ + k0n + ao4);
                }
                CP_COMMIT();
            }
            const float* A_ = smem + (sub % 3) * A1S;
            const float* B_ = smem + B1O + (sub % 3) * B1S;
#pragma unroll
            for (int ks = 0; ks < 4; ks++) {
                int kc = ks * 8 + c;
                float a0 = A_[g * 36 + kc],       a0h = A_[g * 36 + kc + 4];
                float a1 = A_[(g + 8) * 36 + kc], a1h = A_[(g + 8) * 36 + kc + 4];
#pragma unroll
                for (int ni = 0; ni < 2; ni++) {
                    float bx = B_[(nw + ni * 8 + g) * 36 + kc];
                    float by = B_[(nw + ni * 8 + g) * 36 + kc + 4];
                    mma8(acc[ni], a0, a1, a0h, a1h, bx, by);
                }
            }
        }
        // direct store x_lin + fused a_node (smem reduce, direct store)
        float an0 = 0.f, an8 = 0.f;
#pragma unroll
        for (int ni = 0; ni < 2; ni++) {
            int col = nw + ni * 8 + 2 * c;
            *(float2*)&g_xlin[(size_t)(m0 + g) * OC + col]     = make_float2(acc[ni][0], acc[ni][1]);
            *(float2*)&g_xlin[(size_t)(m0 + g + 8) * OC + col] = make_float2(acc[ni][2], acc[ni][3]);
            an0 += acc[ni][0] * sX[col] + acc[ni][1] * sX[col + 1];
            an8 += acc[ni][2] * sX[col] + acc[ni][3] * sX[col + 1];
        }
        an0 += __shfl_xor_sync(0xffffffffu, an0, 1);
        an0 += __shfl_xor_sync(0xffffffffu, an0, 2);
        an8 += __shfl_xor_sync(0xffffffffu, an8, 1);
        an8 += __shfl_xor_sync(0xffffffffu, an8, 2);
        if (c == 0) { atomicAdd(&s_an[g], an0); atomicAdd(&s_an[g + 8], an8); }
        __syncthreads();
        if (t < 16) g_anode[m0 + t] = s_an[t];
    } else if (cta < 240) {
        int b = cta - 160;
        const float* base = (b < 64) ? (cemb + (size_t)b * 32 * IN_)
                                     : (memb + (size_t)(b - 64) * 32 * IN_);
        float s = 0.f;
#pragma unroll
        for (int r = 0; r < 32; r++) s += base[r * IN_ + t];
        atomicAdd((b < 64) ? &g_meanc[t] : &g_meanm[t], s);
    } else if (cta == 240) {
        float s = 0.f;
        for (int o = 0; o < OC; o++) s += Wg[o * IN_ + t] * att[OC + o];
        g_vb[t] = s;
    }
    gsync();

    // ======== Phase 2: softmax (2048 warp-rows) + conv vectors ========
    {
        float* sf = smem;          // sanm[512] + svb[256]
        if (cta < 256) {
            sf[t]       = g_anode[ND + t];
            sf[256 + t] = g_anode[ND + 256 + t];
            sf[512 + t] = g_vb[t];
        }
        __syncthreads();
        if (cta < 256) {
            int d = cta * 8 + w;
            const float* hb = he + (size_t)d * IN_;
            float ah = 0.f;
#pragma unroll
            for (int j = 0; j < 8; j++) { int i = lane + j * 32; ah += hb[i] * sf[512 + i]; }
#pragma unroll
            for (int s = 16; s > 0; s >>= 1) ah += __shfl_xor_sync(0xffffffffu, ah, s);
            float l[16];
            float mx = -1e30f;
#pragma unroll
            for (int j = 0; j < 16; j++) { l[j] = lrelu(sf[lane + j * 32] + ah); mx = fmaxf(mx, l[j]); }
            float l0 = lrelu(g_anode[d] + ah);
            mx = fmaxf(mx, l0);
#pragma unroll
            for (int s = 16; s > 0; s >>= 1) mx = fmaxf(mx, __shfl_xor_sync(0xffffffffu, mx, s));
            float psum = 0.f;
#pragma unroll
            for (int j = 0; j < 16; j++) { l[j] = __expf(l[j] - mx); psum += l[j]; }
#pragma unroll
            for (int s = 16; s > 0; s >>= 1) psum += __shfl_xor_sync(0xffffffffu, psum, s);
            float e0 = __expf(l0 - mx);
            float inv = 1.f / (psum + e0);
#pragma unroll
            for (int j = 0; j < 16; j++) g_E[(size_t)d * NM + lane + j * 32] = l[j] * inv;
            if (lane == 0) g_alpha0[d] = e0 * inv;
        } else if (cta < 288) {
            int gi = (cta - 256) * 8 + w;   // 0-127 convc, 128-255 convm
            int o = gi & 127;
            const float* mean = (gi < 128) ? g_meanc : g_meanm;
            float s = 0.f;
#pragma unroll
            for (int j = 0; j < 8; j++) { int i = lane + j * 32; s += Wc[o * IN_ + i] * mean[i]; }
#pragma unroll
            for (int sh = 16; sh > 0; sh >>= 1) s += __shfl_xor_sync(0xffffffffu, s, sh);
            if (lane == 0) {
                if (gi < 128) g_convc[o] = s * (1.f / ND) + bc[o];
                else          g_convm[o] = s * (1.f / NM) + bc[o];
            }
        }
    }
    gsync();

    // ======== Phase 3: gemm2 partials p2[s] = E[:,ks] @ xlin_med[ks,:] (256 CTAs) ========
    if (cta < 256) {
        int m0 = (cta >> 2) * 32;          // 64 m-tiles of 32
        int ksp = cta & 3;                 // ksplit 4, chunk 128 = 4 subchunks
        int kb = ksp * 128;
        const int am = t >> 3, ao4 = (t & 7) * 4;    // A coords: 32 x 32
        const int bk = w, bn4 = lane * 4;            // B coords: k = i*8+w, n4
        const float* Bb = g_xlin + (size_t)ND * OC;
        float acc[4][4] = {};
#pragma unroll
        for (int p = 0; p < 2; p++) {
            int k0 = kb + p * 32;
            cpa16(smem + p * A3S + am * 36 + ao4, g_E + (size_t)(m0 + am) * NM + k0 + ao4);
#pragma unroll
            for (int i = 0; i < 4; i++)
                cpa16(smem + B3O + p * B3S + (i * 8 + bk) * 136 + bn4,
                      Bb + (size_t)(k0 + i * 8 + bk) * OC + bn4);
            CP_COMMIT();
        }
        for (int sub = 0; sub < 4; sub++) {
            if (sub < 3) CP_WAIT1(); else CP_WAIT0();
            __syncthreads();
            if (sub < 2) {
                int k0n = kb + (sub + 2) * 32, nb = (sub + 2) % 3;
                cpa16(smem + nb * A3S + am * 36 + ao4,
                      g_E + (size_t)(m0 + am) * NM + k0n + ao4);
#pragma unroll
                for (int i = 0; i < 4; i++)
                    cpa16(smem + B3O + nb * B3S + (i * 8 + bk) * 136 + bn4,
                          Bb + (size_t)(k0n + i * 8 + bk) * OC + bn4);
                CP_COMMIT();
            }
            const float* A_ = smem + (sub % 3) * A3S;
            const float* B_ = smem + B3O + (sub % 3) * B3S;
#pragma unroll
            for (int ks = 0; ks < 4; ks++) {
                int kc = ks * 8 + c;
                float a0 = A_[(m0w + g) * 36 + kc],     a0h = A_[(m0w + g) * 36 + kc + 4];
                float a1 = A_[(m0w + g + 8) * 36 + kc], a1h = A_[(m0w + g + 8) * 36 + kc + 4];
#pragma unroll
                for (int ni = 0; ni < 4; ni++) {
                    float bx = B_[kc * 136 + n0w + ni * 8 + g];
                    float by = B_[(kc + 4) * 136 + n0w + ni * 8 + g];
                    mma8(acc[ni], a0, a1, a0h, a1h, bx, by);
                }
            }
        }
        float* dst = g_p2 + (size_t)ksp * NDOC;
        int r0 = m0 + m0w + g;
#pragma unroll
        for (int ni = 0; ni < 4; ni++) {
            int col = n0w + ni * 8 + 2 * c;
            *(float2*)&dst[(size_t)r0 * OC + col]       = make_float2(acc[ni][0], acc[ni][1]);
            *(float2*)&dst[(size_t)(r0 + 8) * OC + col] = make_float2(acc[ni][2], acc[ni][3]);
        }
    }
    gsync();

    // ======== Phase 4: epilogue 1 (sum partials -> e, disease rows) + mean resets ========
    for (int idx = gid; idx < NDOC; idx += tot) {
        int d = idx >> 7, n = idx & 127;
        float p = g_p2[idx] + g_p2[NDOC + idx] + g_p2[2 * NDOC + idx] + g_p2[3 * NDOC + idx];
        float a0 = g_alpha0[d];
        float e  = (a0 * g_xlin[idx] + p) * (1.f / NEDG);
        g_e[idx] = e;
        out[(size_t)d * (2 * OC) + n]      = a0 * e + bg[n];
        out[(size_t)d * (2 * OC) + OC + n] = g_convc[n];
    }
    if (gid < IN_) g_meanc[gid] = 0.f;
    else if (gid < 2 * IN_) g_meanm[gid - IN_] = 0.f;
    gsync();

    // ======== Phase 5: gemm3 partials p3[s] = E^T[:,ks] @ e[ks,:] (256 CTAs) ========
    if (cta < 256) {
        int m0 = (cta >> 4) * 32;          // 16 m-tiles of 32
        int ksp = cta & 15;                // ksplit 16, chunk 128 = 4 subchunks
        int kb = ksp * 128;
        const int ak = t >> 3, am4 = (t & 7) * 4;    // A (E^T): 32 k x 32 m
        const int bk = w, bn4 = lane * 4;
        float acc[4][4] = {};
#pragma unroll
        for (int p = 0; p < 2; p++) {
            int k0 = kb + p * 32;
            cpa16(smem + p * A5S + ak * 40 + am4, g_E + (size_t)(k0 + ak) * NM + m0 + am4);
#pragma unroll
            for (int i = 0; i < 4; i++)
                cpa16(smem + B5O + p * B3S + (i * 8 + bk) * 136 + bn4,
                      g_e + (size_t)(k0 + i * 8 + bk) * OC + bn4);
            CP_COMMIT();
        }
        for (int sub = 0; sub < 4; sub++) {
            if (sub < 3) CP_WAIT1(); else CP_WAIT0();
            __syncthreads();
            if (sub < 2) {
                int k0n = kb + (sub + 2) * 32, nb = (sub + 2) % 3;
                cpa16(smem + nb * A5S + ak * 40 + am4,
                      g_E + (size_t)(k0n + ak) * NM + m0 + am4);
#pragma unroll
                for (int i = 0; i < 4; i++)
                    cpa16(smem + B5O + nb * B3S + (i * 8 + bk) * 136 + bn4,
                          g_e + (size_t)(k0n + i * 8 + bk) * OC + bn4);
                CP_COMMIT();
            }
            const float* A_ = smem + (sub % 3) * A5S;
            const float* B_ = smem + B5O + (sub % 3) * B3S;
#pragma unroll
            for (int ks = 0; ks < 4; ks++) {
                int kc = ks * 8 + c;
                float a0 = A_[kc * 40 + m0w + g],       a0h = A_[(kc + 4) * 40 + m0w + g];
                float a1 = A_[kc * 40 + m0w + g + 8],   a1h = A_[(kc + 4) * 40 + m0w + g + 8];
#pragma unroll
                for (int ni = 0; ni < 4; ni++) {
                    float bx = B_[kc * 136 + n0w + ni * 8 + g];
                    float by = B_[(kc + 4) * 136 + n0w + ni * 8 + g];
                    mma8(acc[ni], a0, a1, a0h, a1h, bx, by);
                }
            }
        }
        float* dst = g_p3 + (size_t)ksp * NMOC;
        int r0 = m0 + m0w + g;
#pragma unroll
        for (int ni = 0; ni < 4; ni++) {
            int col = n0w + ni * 8 + 2 * c;
            *(float2*)&dst[(size_t)r0 * OC + col]       = make_float2(acc[ni][0], acc[ni][1]);
            *(float2*)&dst[(size_t)(r0 + 8) * OC + col] = make_float2(acc[ni][2], acc[ni][3]);
        }
    }
    gsync();

    // ======== Phase 6: epilogue 2 (sum 16 partials -> medicine rows) ========
    for (int idx = gid; idx < NMOC; idx += tot) {
        int m = idx >> 7, n = idx & 127;
        float s = 0.f;
#pragma unroll
        for (int si = 0; si < 16; si++) s += g_p3[(size_t)si * NMOC + idx];
        out[(size_t)(ND + m) * (2 * OC) + n]      = s * (1.f / ND) + bg[n];
        out[(size_t)(ND + m) * (2 * OC) + OC + n] = g_convm[n];
    }
}

// ---------------- launch: ONE kernel, dynamic smem ----------------
extern "C" void kernel_launch(void* const* d_in, const int* in_sizes, int n_in,
                              void* d_out, int out_size) {
    const float* cemb = (const float*)d_in[2];
    const float* memb = (const float*)d_in[3];
    const float* Wc   = (const float*)d_in[4];
    const float* bc   = (const float*)d_in[5];
    const float* Wg   = (const float*)d_in[6];
    const float* att  = (const float*)d_in[7];
    const float* bg   = (const float*)d_in[8];
    const float* he   = (const float*)d_in[9];
    float* out = (float*)d_out;

    cudaFuncSetAttribute(k_fused, cudaFuncAttributeMaxDynamicSharedMemorySize, SMEMB);
    k_fused<<<NCTA, NTHR, SMEMB>>>(cemb, memb, Wc, bc, Wg, att, bg, he, out);
}